// round 12
// baseline (speedup 1.0000x reference)
#include <cuda_runtime.h>
#include <cstdint>
#include <math.h>

#define SEQ 2048
#define HID 2048
#define NB  2
#define NH  16
#define HD  128
#define BH  (NB*NH)          // 32
#define MTOT (NB*SEQ)        // 4096
#define NEGMASK (-(1<<20))
#define NQB (SEQ/128)        // 16
#define NTRI (NQB*(NQB+1)/2) // 136

// ---------------- device scratch ----------------
__device__ unsigned g_x4[MTOT * (HID/4)];
__device__ int g_b32[4 * HID];
__device__ unsigned g_wt[4 * HID * (HID/4)];
__device__ int g_q[BH * SEQ * HD];
__device__ int g_k[BH * SEQ * HD];
__device__ int g_v[BH * SEQ * HD];
__device__ int g_scores[(size_t)BH * SEQ * SEQ];
__device__ int g_rowmax[BH * SEQ];
__device__ unsigned char g_d0[MTOT * HID];
__device__ unsigned char g_d1[MTOT * HID];
__device__ unsigned char g_d2[MTOT * HID];

// ---------------- helpers ----------------
__device__ __forceinline__ void mma_u8s8(int* d, const unsigned* a, const unsigned* b) {
    asm volatile(
        "mma.sync.aligned.m16n8k32.row.col.s32.u8.s8.s32 "
        "{%0,%1,%2,%3},{%4,%5,%6,%7},{%8,%9},{%0,%1,%2,%3};"
        : "+r"(d[0]), "+r"(d[1]), "+r"(d[2]), "+r"(d[3])
        : "r"(a[0]), "r"(a[1]), "r"(a[2]), "r"(a[3]), "r"(b[0]), "r"(b[1]));
}
__device__ __forceinline__ void mma_s8s8(int* d, const unsigned* a, const unsigned* b) {
    asm volatile(
        "mma.sync.aligned.m16n8k32.row.col.s32.s8.s8.s32 "
        "{%0,%1,%2,%3},{%4,%5,%6,%7},{%8,%9},{%0,%1,%2,%3};"
        : "+r"(d[0]), "+r"(d[1]), "+r"(d[2]), "+r"(d[3])
        : "r"(a[0]), "r"(a[1]), "r"(a[2]), "r"(a[3]), "r"(b[0]), "r"(b[1]));
}
__device__ __forceinline__ void ldsm_x4(unsigned* r, unsigned addr) {
    asm volatile("ldmatrix.sync.aligned.m8n8.x4.shared.b16 {%0,%1,%2,%3},[%4];"
                 : "=r"(r[0]), "=r"(r[1]), "=r"(r[2]), "=r"(r[3]) : "r"(addr));
}
__device__ __forceinline__ void ldsm_x2(unsigned* r, unsigned addr) {
    asm volatile("ldmatrix.sync.aligned.m8n8.x2.shared.b16 {%0,%1},[%2];"
                 : "=r"(r[0]), "=r"(r[1]) : "r"(addr));
}
__device__ __forceinline__ void cp16(unsigned smaddr, const void* g) {
    asm volatile("cp.async.cg.shared.global [%0], [%1], 16;" :: "r"(smaddr), "l"(g));
}
#define CP_COMMIT() asm volatile("cp.async.commit_group;" ::: "memory")
#define CP_WAIT1()  asm volatile("cp.async.wait_group 1;" ::: "memory")
#define CP_WAIT0()  asm volatile("cp.async.wait_group 0;" ::: "memory")

// ---------------- dtype detection ----------------
__device__ __forceinline__ int classify_word(unsigned w) {
    if (w == 0u) return -1;
    int iv = (int)w;
    if (iv >= -520 && iv <= 520) return 0;
    float f = __int_as_float(w);
    if (isfinite(f) && fabsf(f) <= 520.0f && f != 0.0f && f == rintf(f)) return 1;
    return 2;
}
__device__ int detect_dtype(const unsigned* w, int nwords) {
    __shared__ int votes[3];
    if (threadIdx.x < 3) votes[threadIdx.x] = 0;
    __syncthreads();
    int local[3] = {0,0,0};
    for (int i = threadIdx.x; i < nwords; i += blockDim.x) {
        int c = classify_word(w[i]);
        if (c >= 0) local[c]++;
    }
    for (int c = 0; c < 3; c++) if (local[c]) atomicAdd(&votes[c], local[c]);
    __syncthreads();
    int best = 0;
    if (votes[1] > votes[best]) best = 1;
    if (votes[2] > votes[best]) best = 2;
    return best;
}

// ---------------- ONE conversion kernel: weights(+biases) y=0..3, x(+rowmax init) y=4 ----------------
#define WBLOCKS ((HID*(HID/4) + 255)/256)    // 4096
#define XBLOCKS ((MTOT*(HID/4) + 255)/256)   // 8192
__global__ void convall_kernel(const void* xp,
                               const void* w0, const void* w1, const void* w2, const void* w3,
                               const void* b0, const void* b1, const void* b2, const void* b3) {
    int y = blockIdx.y;
    if (y == 4) {
        // x conversion + rowmax init
        int flag = detect_dtype((const unsigned*)xp, 1024);
        int i = blockIdx.x * blockDim.x + threadIdx.x;
        if (i < BH*SEQ) g_rowmax[i] = (int)0x80000000;
        if (i >= MTOT * (HID/4)) return;
        unsigned a, b, c, d;
        if (flag == 1) {
            float4 v = reinterpret_cast<const float4*>(xp)[i];
            a = (unsigned)(int)v.x; b = (unsigned)(int)v.y;
            c = (unsigned)(int)v.z; d = (unsigned)(int)v.w;
        } else {
            int4 v = reinterpret_cast<const int4*>(xp)[i];
            a = (unsigned)v.x; b = (unsigned)v.y; c = (unsigned)v.z; d = (unsigned)v.w;
        }
        g_x4[i] = (a & 255u) | ((b & 255u) << 8) | ((c & 255u) << 16) | ((d & 255u) << 24);
        return;
    }
    int slot = y;
    const void* ws[4] = {w0, w1, w2, w3};
    const void* bs[4] = {b0, b1, b2, b3};
    if ((int)blockIdx.x < WBLOCKS) {
        const void* wp = ws[slot];
        int flag = detect_dtype((const unsigned*)wp, 1024);
        int i = blockIdx.x * blockDim.x + threadIdx.x;
        if (i >= HID * (HID/4)) return;
        int kw = i >> 11;
        int n  = i & (HID-1);
        unsigned b[4];
        if (flag == 2) {
            const unsigned char* p = (const unsigned char*)wp;
#pragma unroll
            for (int j = 0; j < 4; j++) b[j] = p[(size_t)(4*kw+j)*HID + n];
        } else if (flag == 1) {
            const float* p = (const float*)wp;
#pragma unroll
            for (int j = 0; j < 4; j++) b[j] = (unsigned)(int)p[(size_t)(4*kw+j)*HID + n] & 255u;
        } else {
            const int* p = (const int*)wp;
#pragma unroll
            for (int j = 0; j < 4; j++) b[j] = (unsigned)p[(size_t)(4*kw+j)*HID + n] & 255u;
        }
        g_wt[(size_t)slot * (HID*(HID/4)) + (size_t)n*(HID/4) + kw] =
            b[0] | (b[1]<<8) | (b[2]<<16) | (b[3]<<24);
    } else if ((int)blockIdx.x < WBLOCKS + 8) {
        const void* bp = bs[slot];
        int flag = detect_dtype((const unsigned*)bp, 512);
        int i = ((int)blockIdx.x - WBLOCKS) * blockDim.x + threadIdx.x;
        if (i >= HID) return;
        int v;
        if (flag == 1) v = (int)reinterpret_cast<const float*>(bp)[i];
        else           v = reinterpret_cast<const int*>(bp)[i];
        g_b32[slot * HID + i] = v;
    }
}

// ---------------- QKV projection: IMMA + cp.async double buffer ----------------
__global__ __launch_bounds__(256) void proj_imma_kernel() {
    __shared__ unsigned char As[2][128*80];
    __shared__ unsigned char Bs[2][128*80];
    int slot = blockIdx.z;
    const unsigned* W4 = g_wt + (size_t)slot * (HID*(HID/4));
    const int* bias = g_b32 + slot * HID;
    int* outp = (slot == 0) ? g_q : (slot == 1) ? g_k : g_v;

    int bn = blockIdx.x;
    int bm = blockIdx.y;
    int t = threadIdx.x, lane = t & 31, warp = t >> 5;
    int wm = warp >> 2, wn = warp & 3;

    unsigned aB = (unsigned)__cvta_generic_to_shared(As);
    unsigned bB = (unsigned)__cvta_generic_to_shared(Bs);

    int acc[4][4][4];
#pragma unroll
    for (int i = 0; i < 4; i++)
#pragma unroll
        for (int j = 0; j < 4; j++)
#pragma unroll
            for (int r = 0; r < 4; r++) acc[i][j][r] = 0;

    int lrowA = (lane & 7) + ((lane >> 3) & 1) * 8;
    int lkoffA = (lane >= 16) ? 16 : 0;
    int lrowB = (lane & 7);
    int lkoffB = ((lane >> 3) & 1) * 16;

    #define PJ_STAGE(ks, buf)                                                              \
        do {                                                                               \
            for (int idx = t; idx < 512; idx += 256) {                                     \
                int row = idx >> 2, q = idx & 3;                                           \
                cp16(aB + (buf)*10240 + row*80 + q*16,                                     \
                     &g_x4[(size_t)(bm*128 + row)*512 + (ks)*16 + q*4]);                   \
                cp16(bB + (buf)*10240 + row*80 + q*16,                                     \
                     &W4[(size_t)(bn*128 + row)*512 + (ks)*16 + q*4]);                     \
            }                                                                              \
            CP_COMMIT();                                                                   \
        } while (0)

    PJ_STAGE(0, 0);
    for (int ks = 0; ks < 32; ks++) {
        int buf = ks & 1;
        if (ks < 31) { PJ_STAGE(ks + 1, buf ^ 1); CP_WAIT1(); }
        else         { CP_WAIT0(); }
        __syncthreads();
#pragma unroll
        for (int kk = 0; kk < 2; kk++) {
            unsigned bfr[4][2];
#pragma unroll
            for (int nf = 0; nf < 4; nf++)
                ldsm_x2(bfr[nf], bB + buf*10240 + (wn*32 + nf*8 + lrowB)*80 + kk*32 + lkoffB);
            unsigned afr[4][4];
#pragma unroll
            for (int mf = 0; mf < 4; mf++)
                ldsm_x4(afr[mf], aB + buf*10240 + (wm*64 + mf*16 + lrowA)*80 + kk*32 + lkoffA);
#pragma unroll
            for (int mf = 0; mf < 4; mf++)
#pragma unroll
                for (int nf = 0; nf < 4; nf++)
                    mma_u8s8(acc[mf][nf], afr[mf], bfr[nf]);
        }
        __syncthreads();
    }
    #undef PJ_STAGE

#pragma unroll
    for (int mf = 0; mf < 4; mf++) {
#pragma unroll
        for (int nf = 0; nf < 4; nf++) {
            int n = bn*128 + wn*32 + nf*8 + 2*(lane & 3);
            int h = n >> 7, d = n & (HD-1);
            int bia0 = bias[n], bia1 = bias[n+1];
#pragma unroll
            for (int half = 0; half < 2; half++) {
                int r = bm*128 + wm*64 + mf*16 + (lane >> 2) + half*8;
                int b = r >> 11, s = r & (SEQ-1);
                int v0 = (acc[mf][nf][half*2+0] + bia0) >> 6;
                int v1 = (acc[mf][nf][half*2+1] + bia1) >> 6;
                *reinterpret_cast<int2*>(&outp[((size_t)(b*NH + h)*SEQ + s)*HD + d]) = make_int2(v0, v1);
            }
        }
    }
}

// ---------------- QK scores: 128x128 IMAD, 8x8 regs + fused rowmax ----------------
__global__ __launch_bounds__(256) void qk_gemm_kernel() {
    __shared__ int As[32][132];
    __shared__ int Bs[32][132];

    int bh = blockIdx.y;
    int blk = blockIdx.x;
    int qi = (int)((sqrtf(8.0f*blk + 1.0f) - 1.0f) * 0.5f);
    while ((qi+1)*(qi+2)/2 <= blk) qi++;
    while (qi*(qi+1)/2 > blk) qi--;
    int ki = blk - qi*(qi+1)/2;

    const int* Qb = g_q + (size_t)bh*SEQ*HD + (size_t)(qi*128)*HD;
    const int* Kb = g_k + (size_t)bh*SEQ*HD + (size_t)(ki*128)*HD;
    int t = threadIdx.x;
    int rg = t >> 4, cg = t & 15;

    unsigned acc[8][8];
#pragma unroll
    for (int i = 0; i < 8; i++)
#pragma unroll
        for (int j = 0; j < 8; j++) acc[i][j] = 0u;

    for (int ch = 0; ch < 4; ch++) {
        for (int i = t; i < 128*8; i += 256) {
            int row = i >> 3, g = i & 7;
            int4 qv = *reinterpret_cast<const int4*>(&Qb[row*HD + ch*32 + g*4]);
            As[g*4+0][row] = qv.x; As[g*4+1][row] = qv.y;
            As[g*4+2][row] = qv.z; As[g*4+3][row] = qv.w;
            int4 kv = *reinterpret_cast<const int4*>(&Kb[row*HD + ch*32 + g*4]);
            Bs[g*4+0][row] = kv.x; Bs[g*4+1][row] = kv.y;
            Bs[g*4+2][row] = kv.z; Bs[g*4+3][row] = kv.w;
        }
        __syncthreads();

#pragma unroll 4
        for (int d = 0; d < 32; d++) {
            int4 av0 = *reinterpret_cast<const int4*>(&As[d][rg*8]);
            int4 av1 = *reinterpret_cast<const int4*>(&As[d][rg*8+4]);
            int4 bv0 = *reinterpret_cast<const int4*>(&Bs[d][cg*8]);
            int4 bv1 = *reinterpret_cast<const int4*>(&Bs[d][cg*8+4]);
            int a[8] = {av0.x, av0.y, av0.z, av0.w, av1.x, av1.y, av1.z, av1.w};
            int b[8] = {bv0.x, bv0.y, bv0.z, bv0.w, bv1.x, bv1.y, bv1.z, bv1.w};
#pragma unroll
            for (int i = 0; i < 8; i++)
#pragma unroll
                for (int j = 0; j < 8; j++)
                    acc[i][j] += (unsigned)a[i] * (unsigned)b[j];
        }
        __syncthreads();
    }

    int rowbase = qi*128 + rg*8;
    int colbase = ki*128 + cg*8;
    int* dst = g_scores + (size_t)bh*SEQ*SEQ + (size_t)rowbase*SEQ + colbase;
#pragma unroll
    for (int i = 0; i < 8; i++) {
        *reinterpret_cast<int4*>(dst + (size_t)i*SEQ) =
            make_int4(((int)acc[i][0]) >> 1, ((int)acc[i][1]) >> 1,
                      ((int)acc[i][2]) >> 1, ((int)acc[i][3]) >> 1);
        *reinterpret_cast<int4*>(dst + (size_t)i*SEQ + 4) =
            make_int4(((int)acc[i][4]) >> 1, ((int)acc[i][5]) >> 1,
                      ((int)acc[i][6]) >> 1, ((int)acc[i][7]) >> 1);
    }

    // fused per-row max (causal masked), 16-lane reduce, one atomicMax per row
#pragma unroll
    for (int i = 0; i < 8; i++) {
        int row = rowbase + i;
        int mx = (int)0x80000000;
#pragma unroll
        for (int j = 0; j < 8; j++) {
            int col = colbase + j;
            int v = ((int)acc[i][j]) >> 1;
            if (col <= row) mx = max(mx, v);
        }
#pragma unroll
        for (int off = 1; off < 16; off <<= 1)
            mx = max(mx, __shfl_xor_sync(0xffffffffu, mx, off));
        if (cg == 0 && mx != (int)0x80000000)
            atomicMax(&g_rowmax[bh*SEQ + row], mx);
    }
}

// ---------------- sparse AV (warp per row; rowmax precomputed) -> digit planes ----------------
__global__ __launch_bounds__(256) void av_kernel() {
    int t = threadIdx.x, lane = t & 31, warp = t >> 5;
    int bh = blockIdx.y;
    int qr = blockIdx.x * 8 + warp;
    const int* srow = g_scores + (size_t)bh*SEQ*SEQ + (size_t)qr*SEQ;
    const int* Vb = g_v + (size_t)bh * SEQ * HD;

    int m = g_rowmax[bh*SEQ + qr];
    bool hasMasked = (qr < SEQ - 1);
    if (hasMasked) m = max(m, NEGMASK);

    unsigned acc[4] = {0u, 0u, 0u, 0u};
    int d0 = lane * 4;

    // candidate pass, int4-vectorized: 128 cols per warp-trip
    for (int k0 = 0; k0 <= qr; k0 += 128) {
        int kb = k0 + lane*4;
        int4 sv = *reinterpret_cast<const int4*>(&srow[kb]);
        int a4[4];
        a4[0] = (kb+0 <= qr) ? min(sv.x - m + 256, 4095) : 0;
        a4[1] = (kb+1 <= qr) ? min(sv.y - m + 256, 4095) : 0;
        a4[2] = (kb+2 <= qr) ? min(sv.z - m + 256, 4095) : 0;
        a4[3] = (kb+3 <= qr) ? min(sv.w - m + 256, 4095) : 0;
#pragma unroll
        for (int e = 0; e < 4; e++) {
            int a = a4[e];
            unsigned mask = __ballot_sync(0xffffffffu, a > 0);
            while (mask) {
                int src = __ffs(mask) - 1;
                mask &= mask - 1;
                unsigned aa = (unsigned)__shfl_sync(0xffffffffu, a, src);
                int kk = k0 + src*4 + e;
                int4 v = *reinterpret_cast<const int4*>(&Vb[kk*HD + d0]);
                acc[0] += aa * (unsigned)v.x; acc[1] += aa * (unsigned)v.y;
                acc[2] += aa * (unsigned)v.z; acc[3] += aa * (unsigned)v.w;
            }
        }
    }

    int am = NEGMASK - m + 256;
    if (am > 4095) am = 4095;
    if (hasMasked && am > 0) {
        for (int k = qr + 1; k < SEQ; k++) {
            int4 v = *reinterpret_cast<const int4*>(&Vb[k*HD + d0]);
            unsigned ua = (unsigned)am;
            acc[0] += ua * (unsigned)v.x; acc[1] += ua * (unsigned)v.y;
            acc[2] += ua * (unsigned)v.z; acc[3] += ua * (unsigned)v.w;
        }
    }

    unsigned p0 = 0, p1 = 0, p2 = 0;
#pragma unroll
    for (int j = 0; j < 4; j++) {
        int v = ((int)acc[j]) >> 12;
        int dd0 = (int)(signed char)(v & 0xff);
        int r1 = (v - dd0) >> 8;
        int dd1 = (int)(signed char)(r1 & 0xff);
        int dd2 = (r1 - dd1) >> 8;
        p0 |= ((unsigned)dd0 & 255u) << (8*j);
        p1 |= ((unsigned)dd1 & 255u) << (8*j);
        p2 |= ((unsigned)dd2 & 255u) << (8*j);
    }
    int b = bh >> 4, h = bh & (NH-1);
    size_t off = (((size_t)(b*SEQ + qr))*HID + h*HD + d0) >> 2;
    reinterpret_cast<unsigned*>(g_d0)[off] = p0;
    reinterpret_cast<unsigned*>(g_d1)[off] = p1;
    reinterpret_cast<unsigned*>(g_d2)[off] = p2;
}

// ---------------- output projection: IMMA digit planes + cp.async double buffer ----------------
__global__ __launch_bounds__(256) void out_imma_kernel(float* __restrict__ out) {
    __shared__ unsigned char Ap[2][3][64*48];
    __shared__ unsigned char Bs[2][64*48];
    const unsigned* W4 = g_wt + (size_t)3 * (HID*(HID/4));
    const int* bias = g_b32 + 3 * HID;

    int bn = blockIdx.x;
    int bm = blockIdx.y;
    int t = threadIdx.x, lane = t & 31, warp = t >> 5;
    int wm = warp >> 2, wn = warp & 3;

    unsigned aB = (unsigned)__cvta_generic_to_shared(Ap);
    unsigned bB = (unsigned)__cvta_generic_to_shared(Bs);

    int acc[2][2][3][4];
#pragma unroll
    for (int i = 0; i < 2; i++)
#pragma unroll
        for (int j = 0; j < 2; j++)
#pragma unroll
            for (int l = 0; l < 3; l++)
#pragma unroll
                for (int r = 0; r < 4; r++) acc[i][j][l][r] = 0;

    int lrowA = (lane & 7) + ((lane >> 3) & 1) * 8;
    int lkoffA = (lane >= 16) ? 16 : 0;
    int lrowB = (lane & 7);
    int lkoffB = ((lane >> 3) & 1) * 16;

    const unsigned char* P[3] = {g_d0, g_d1, g_d2};

    #define OT_STAGE(ks, buf)                                                              \
        do {                                                                               \
            for (int idx = t; idx < 384; idx += 256) {                                     \
                int l = idx >> 7, j = idx & 127, row = j >> 1, half = j & 1;               \
                cp16(aB + (buf)*9216 + l*3072 + row*48 + half*16,                          \
                     P[l] + ((size_t)(bm*64 + row))*HID + (ks)*32 + half*16);              \
            }                                                                              \
            for (int idx = t; idx < 128; idx += 256) {                                     \
                int row = idx >> 1, half = idx & 1;                                        \
                cp16(bB + (buf)*3072 + row*48 + half*16,                                   \
                     &W4[(size_t)(bn*64 + row)*512 + (ks)*8 + half*4]);                    \
            }                                                                              \
            CP_COMMIT();                                                                   \
        } while (0)

    OT_STAGE(0, 0);
    for (int ks = 0; ks < 64; ks++) {
        int buf = ks & 1;
        if (ks < 63) { OT_STAGE(ks + 1, buf ^ 1); CP_WAIT1(); }
        else         { CP_WAIT0(); }
        __syncthreads();

        unsigned bfr[2][2];
#pragma unroll
        for (int nf = 0; nf < 2; nf++)
            ldsm_x2(bfr[nf], bB + buf*3072 + (wn*16 + nf*8 + lrowB)*48 + lkoffB);
#pragma unroll
        for (int mf = 0; mf < 2; mf++) {
#pragma unroll
            for (int l = 0; l < 3; l++) {
                unsigned afr[4];
                ldsm_x4(afr, aB + buf*9216 + l*3072 + (wm*32 + mf*16 + lrowA)*48 + lkoffA);
#pragma unroll
                for (int nf = 0; nf < 2; nf++)
                    mma_s8s8(acc[mf][nf][l], afr, bfr[nf]);
            }
        }
        __syncthreads();
    }
    #undef OT_STAGE

#pragma unroll
    for (int mf = 0; mf < 2; mf++) {
#pragma unroll
        for (int nf = 0; nf < 2; nf++) {
            int n = bn*64 + wn*16 + nf*8 + 2*(lane & 3);
            unsigned bia0 = (unsigned)bias[n], bia1 = (unsigned)bias[n+1];
#pragma unroll
            for (int half = 0; half < 2; half++) {
                int r = bm*64 + wm*32 + mf*16 + (lane >> 2) + half*8;
                unsigned u0 = (unsigned)acc[mf][nf][0][half*2+0]
                            + ((unsigned)acc[mf][nf][1][half*2+0] << 8)
                            + ((unsigned)acc[mf][nf][2][half*2+0] << 16) + bia0;
                unsigned u1 = (unsigned)acc[mf][nf][0][half*2+1]
                            + ((unsigned)acc[mf][nf][1][half*2+1] << 8)
                            + ((unsigned)acc[mf][nf][2][half*2+1] << 16) + bia1;
                float2 fv = make_float2((float)(((int)u0) >> 7), (float)(((int)u1) >> 7));
                *reinterpret_cast<float2*>(&out[(size_t)r*HID + n]) = fv;
            }
        }
    }
}

// ---------------- launch ----------------
extern "C" void kernel_launch(void* const* d_in, const int* in_sizes, int n_in,
                              void* d_out, int out_size) {
    const void* x  = d_in[0];
    const void* wq = d_in[1]; const void* bq = d_in[2];
    const void* wk = d_in[3]; const void* bk = d_in[4];
    const void* wv = d_in[5]; const void* bv = d_in[6];
    const void* wo = d_in[7]; const void* bo = d_in[8];
    float* out = (float*)d_out;

    convall_kernel<<<dim3(XBLOCKS, 5), 256>>>(x, wq, wk, wv, wo, bq, bk, bv, bo);     // 1
    proj_imma_kernel<<<dim3(16, 32, 3), 256>>>();                                     // 2
    qk_gemm_kernel<<<dim3(NTRI, BH), 256>>>();                                        // 3
    av_kernel<<<dim3(SEQ/8, BH), 256>>>();                                            // 4 (profiled)
    out_imma_kernel<<<dim3(32, 64), 256>>>(out);                                      // 5
}

// round 13
// speedup vs baseline: 1.0383x; 1.0383x over previous
#include <cuda_runtime.h>
#include <cstdint>
#include <math.h>

#define SEQ 2048
#define HID 2048
#define NB  2
#define NH  16
#define HD  128
#define BH  (NB*NH)          // 32
#define MTOT (NB*SEQ)        // 4096
#define NEGMASK (-(1<<20))
#define NQB (SEQ/128)        // 16
#define NTRI (NQB*(NQB+1)/2) // 136

// ---------------- device scratch ----------------
__device__ unsigned g_x4[MTOT * (HID/4)];
__device__ int g_b32[4 * HID];
__device__ unsigned g_wt[4 * HID * (HID/4)];
__device__ int g_q[BH * SEQ * HD];
__device__ int g_k[BH * SEQ * HD];
__device__ int g_v[BH * SEQ * HD];
__device__ int g_scores[(size_t)BH * SEQ * SEQ];
__device__ int g_rowmax[BH * SEQ];
__device__ unsigned char g_d0[MTOT * HID];
__device__ unsigned char g_d1[MTOT * HID];
__device__ unsigned char g_d2[MTOT * HID];

// ---------------- helpers ----------------
__device__ __forceinline__ void mma_u8s8(int* d, const unsigned* a, const unsigned* b) {
    asm volatile(
        "mma.sync.aligned.m16n8k32.row.col.s32.u8.s8.s32 "
        "{%0,%1,%2,%3},{%4,%5,%6,%7},{%8,%9},{%0,%1,%2,%3};"
        : "+r"(d[0]), "+r"(d[1]), "+r"(d[2]), "+r"(d[3])
        : "r"(a[0]), "r"(a[1]), "r"(a[2]), "r"(a[3]), "r"(b[0]), "r"(b[1]));
}
__device__ __forceinline__ void mma_s8s8(int* d, const unsigned* a, const unsigned* b) {
    asm volatile(
        "mma.sync.aligned.m16n8k32.row.col.s32.s8.s8.s32 "
        "{%0,%1,%2,%3},{%4,%5,%6,%7},{%8,%9},{%0,%1,%2,%3};"
        : "+r"(d[0]), "+r"(d[1]), "+r"(d[2]), "+r"(d[3])
        : "r"(a[0]), "r"(a[1]), "r"(a[2]), "r"(a[3]), "r"(b[0]), "r"(b[1]));
}
__device__ __forceinline__ void ldsm_x4(unsigned* r, unsigned addr) {
    asm volatile("ldmatrix.sync.aligned.m8n8.x4.shared.b16 {%0,%1,%2,%3},[%4];"
                 : "=r"(r[0]), "=r"(r[1]), "=r"(r[2]), "=r"(r[3]) : "r"(addr));
}
__device__ __forceinline__ void ldsm_x2(unsigned* r, unsigned addr) {
    asm volatile("ldmatrix.sync.aligned.m8n8.x2.shared.b16 {%0,%1},[%2];"
                 : "=r"(r[0]), "=r"(r[1]) : "r"(addr));
}
__device__ __forceinline__ void cp16(unsigned smaddr, const void* g) {
    asm volatile("cp.async.cg.shared.global [%0], [%1], 16;" :: "r"(smaddr), "l"(g));
}
#define CP_COMMIT() asm volatile("cp.async.commit_group;" ::: "memory")
#define CP_WAIT1()  asm volatile("cp.async.wait_group 1;" ::: "memory")
#define CP_WAIT0()  asm volatile("cp.async.wait_group 0;" ::: "memory")

// ---------------- dtype detection ----------------
__device__ __forceinline__ int classify_word(unsigned w) {
    if (w == 0u) return -1;
    int iv = (int)w;
    if (iv >= -520 && iv <= 520) return 0;
    float f = __int_as_float(w);
    if (isfinite(f) && fabsf(f) <= 520.0f && f != 0.0f && f == rintf(f)) return 1;
    return 2;
}
__device__ int detect_dtype(const unsigned* w, int nwords) {
    __shared__ int votes[3];
    if (threadIdx.x < 3) votes[threadIdx.x] = 0;
    __syncthreads();
    int local[3] = {0,0,0};
    for (int i = threadIdx.x; i < nwords; i += blockDim.x) {
        int c = classify_word(w[i]);
        if (c >= 0) local[c]++;
    }
    for (int c = 0; c < 3; c++) if (local[c]) atomicAdd(&votes[c], local[c]);
    __syncthreads();
    int best = 0;
    if (votes[1] > votes[best]) best = 1;
    if (votes[2] > votes[best]) best = 2;
    return best;
}

// ---------------- ONE conversion kernel: weights(+biases) y=0..3, x(+rowmax init) y=4 ----------------
#define WBLOCKS ((HID*(HID/4) + 255)/256)    // 4096
#define XBLOCKS ((MTOT*(HID/4) + 255)/256)   // 8192
__global__ void convall_kernel(const void* xp,
                               const void* w0, const void* w1, const void* w2, const void* w3,
                               const void* b0, const void* b1, const void* b2, const void* b3) {
    int y = blockIdx.y;
    if (y == 4) {
        int flag = detect_dtype((const unsigned*)xp, 1024);
        int i = blockIdx.x * blockDim.x + threadIdx.x;
        if (i < BH*SEQ) g_rowmax[i] = (int)0x80000000;
        if (i >= MTOT * (HID/4)) return;
        unsigned a, b, c, d;
        if (flag == 1) {
            float4 v = reinterpret_cast<const float4*>(xp)[i];
            a = (unsigned)(int)v.x; b = (unsigned)(int)v.y;
            c = (unsigned)(int)v.z; d = (unsigned)(int)v.w;
        } else {
            int4 v = reinterpret_cast<const int4*>(xp)[i];
            a = (unsigned)v.x; b = (unsigned)v.y; c = (unsigned)v.z; d = (unsigned)v.w;
        }
        g_x4[i] = (a & 255u) | ((b & 255u) << 8) | ((c & 255u) << 16) | ((d & 255u) << 24);
        return;
    }
    int slot = y;
    const void* ws[4] = {w0, w1, w2, w3};
    const void* bs[4] = {b0, b1, b2, b3};
    if ((int)blockIdx.x < WBLOCKS) {
        const void* wp = ws[slot];
        int flag = detect_dtype((const unsigned*)wp, 1024);
        int i = blockIdx.x * blockDim.x + threadIdx.x;
        if (i >= HID * (HID/4)) return;
        int kw = i >> 11;
        int n  = i & (HID-1);
        unsigned b[4];
        if (flag == 2) {
            const unsigned char* p = (const unsigned char*)wp;
#pragma unroll
            for (int j = 0; j < 4; j++) b[j] = p[(size_t)(4*kw+j)*HID + n];
        } else if (flag == 1) {
            const float* p = (const float*)wp;
#pragma unroll
            for (int j = 0; j < 4; j++) b[j] = (unsigned)(int)p[(size_t)(4*kw+j)*HID + n] & 255u;
        } else {
            const int* p = (const int*)wp;
#pragma unroll
            for (int j = 0; j < 4; j++) b[j] = (unsigned)p[(size_t)(4*kw+j)*HID + n] & 255u;
        }
        g_wt[(size_t)slot * (HID*(HID/4)) + (size_t)n*(HID/4) + kw] =
            b[0] | (b[1]<<8) | (b[2]<<16) | (b[3]<<24);
    } else if ((int)blockIdx.x < WBLOCKS + 8) {
        const void* bp = bs[slot];
        int flag = detect_dtype((const unsigned*)bp, 512);
        int i = ((int)blockIdx.x - WBLOCKS) * blockDim.x + threadIdx.x;
        if (i >= HID) return;
        int v;
        if (flag == 1) v = (int)reinterpret_cast<const float*>(bp)[i];
        else           v = reinterpret_cast<const int*>(bp)[i];
        g_b32[slot * HID + i] = v;
    }
}

// ---------------- QKV projection: IMMA + cp.async double buffer ----------------
__global__ __launch_bounds__(256) void proj_imma_kernel() {
    __shared__ unsigned char As[2][128*80];
    __shared__ unsigned char Bs[2][128*80];
    int slot = blockIdx.z;
    const unsigned* W4 = g_wt + (size_t)slot * (HID*(HID/4));
    const int* bias = g_b32 + slot * HID;
    int* outp = (slot == 0) ? g_q : (slot == 1) ? g_k : g_v;

    int bn = blockIdx.x;
    int bm = blockIdx.y;
    int t = threadIdx.x, lane = t & 31, warp = t >> 5;
    int wm = warp >> 2, wn = warp & 3;

    unsigned aB = (unsigned)__cvta_generic_to_shared(As);
    unsigned bB = (unsigned)__cvta_generic_to_shared(Bs);

    int acc[4][4][4];
#pragma unroll
    for (int i = 0; i < 4; i++)
#pragma unroll
        for (int j = 0; j < 4; j++)
#pragma unroll
            for (int r = 0; r < 4; r++) acc[i][j][r] = 0;

    int lrowA = (lane & 7) + ((lane >> 3) & 1) * 8;
    int lkoffA = (lane >= 16) ? 16 : 0;
    int lrowB = (lane & 7);
    int lkoffB = ((lane >> 3) & 1) * 16;

    #define PJ_STAGE(ks, buf)                                                              \
        do {                                                                               \
            for (int idx = t; idx < 512; idx += 256) {                                     \
                int row = idx >> 2, q = idx & 3;                                           \
                cp16(aB + (buf)*10240 + row*80 + q*16,                                     \
                     &g_x4[(size_t)(bm*128 + row)*512 + (ks)*16 + q*4]);                   \
                cp16(bB + (buf)*10240 + row*80 + q*16,                                     \
                     &W4[(size_t)(bn*128 + row)*512 + (ks)*16 + q*4]);                     \
            }                                                                              \
            CP_COMMIT();                                                                   \
        } while (0)

    PJ_STAGE(0, 0);
    for (int ks = 0; ks < 32; ks++) {
        int buf = ks & 1;
        if (ks < 31) { PJ_STAGE(ks + 1, buf ^ 1); CP_WAIT1(); }
        else         { CP_WAIT0(); }
        __syncthreads();
#pragma unroll
        for (int kk = 0; kk < 2; kk++) {
            unsigned bfr[4][2];
#pragma unroll
            for (int nf = 0; nf < 4; nf++)
                ldsm_x2(bfr[nf], bB + buf*10240 + (wn*32 + nf*8 + lrowB)*80 + kk*32 + lkoffB);
            unsigned afr[4][4];
#pragma unroll
            for (int mf = 0; mf < 4; mf++)
                ldsm_x4(afr[mf], aB + buf*10240 + (wm*64 + mf*16 + lrowA)*80 + kk*32 + lkoffA);
#pragma unroll
            for (int mf = 0; mf < 4; mf++)
#pragma unroll
                for (int nf = 0; nf < 4; nf++)
                    mma_u8s8(acc[mf][nf], afr[mf], bfr[nf]);
        }
        __syncthreads();
    }
    #undef PJ_STAGE

#pragma unroll
    for (int mf = 0; mf < 4; mf++) {
#pragma unroll
        for (int nf = 0; nf < 4; nf++) {
            int n = bn*128 + wn*32 + nf*8 + 2*(lane & 3);
            int h = n >> 7, d = n & (HD-1);
            int bia0 = bias[n], bia1 = bias[n+1];
#pragma unroll
            for (int half = 0; half < 2; half++) {
                int r = bm*128 + wm*64 + mf*16 + (lane >> 2) + half*8;
                int b = r >> 11, s = r & (SEQ-1);
                int v0 = (acc[mf][nf][half*2+0] + bia0) >> 6;
                int v1 = (acc[mf][nf][half*2+1] + bia1) >> 6;
                *reinterpret_cast<int2*>(&outp[((size_t)(b*NH + h)*SEQ + s)*HD + d]) = make_int2(v0, v1);
            }
        }
    }
}

// ---------------- QK scores: 128x128 IMAD, 8x8 regs + fused rowmax ----------------
__global__ __launch_bounds__(256) void qk_gemm_kernel() {
    __shared__ int As[32][132];
    __shared__ int Bs[32][132];

    int bh = blockIdx.y;
    int blk = blockIdx.x;
    int qi = (int)((sqrtf(8.0f*blk + 1.0f) - 1.0f) * 0.5f);
    while ((qi+1)*(qi+2)/2 <= blk) qi++;
    while (qi*(qi+1)/2 > blk) qi--;
    int ki = blk - qi*(qi+1)/2;

    const int* Qb = g_q + (size_t)bh*SEQ*HD + (size_t)(qi*128)*HD;
    const int* Kb = g_k + (size_t)bh*SEQ*HD + (size_t)(ki*128)*HD;
    int t = threadIdx.x;
    int rg = t >> 4, cg = t & 15;

    unsigned acc[8][8];
#pragma unroll
    for (int i = 0; i < 8; i++)
#pragma unroll
        for (int j = 0; j < 8; j++) acc[i][j] = 0u;

    for (int ch = 0; ch < 4; ch++) {
        for (int i = t; i < 128*8; i += 256) {
            int row = i >> 3, g = i & 7;
            int4 qv = *reinterpret_cast<const int4*>(&Qb[row*HD + ch*32 + g*4]);
            As[g*4+0][row] = qv.x; As[g*4+1][row] = qv.y;
            As[g*4+2][row] = qv.z; As[g*4+3][row] = qv.w;
            int4 kv = *reinterpret_cast<const int4*>(&Kb[row*HD + ch*32 + g*4]);
            Bs[g*4+0][row] = kv.x; Bs[g*4+1][row] = kv.y;
            Bs[g*4+2][row] = kv.z; Bs[g*4+3][row] = kv.w;
        }
        __syncthreads();

#pragma unroll 4
        for (int d = 0; d < 32; d++) {
            int4 av0 = *reinterpret_cast<const int4*>(&As[d][rg*8]);
            int4 av1 = *reinterpret_cast<const int4*>(&As[d][rg*8+4]);
            int4 bv0 = *reinterpret_cast<const int4*>(&Bs[d][cg*8]);
            int4 bv1 = *reinterpret_cast<const int4*>(&Bs[d][cg*8+4]);
            int a[8] = {av0.x, av0.y, av0.z, av0.w, av1.x, av1.y, av1.z, av1.w};
            int b[8] = {bv0.x, bv0.y, bv0.z, bv0.w, bv1.x, bv1.y, bv1.z, bv1.w};
#pragma unroll
            for (int i = 0; i < 8; i++)
#pragma unroll
                for (int j = 0; j < 8; j++)
                    acc[i][j] += (unsigned)a[i] * (unsigned)b[j];
        }
        __syncthreads();
    }

    int rowbase = qi*128 + rg*8;
    int colbase = ki*128 + cg*8;
    int* dst = g_scores + (size_t)bh*SEQ*SEQ + (size_t)rowbase*SEQ + colbase;
#pragma unroll
    for (int i = 0; i < 8; i++) {
        *reinterpret_cast<int4*>(dst + (size_t)i*SEQ) =
            make_int4(((int)acc[i][0]) >> 1, ((int)acc[i][1]) >> 1,
                      ((int)acc[i][2]) >> 1, ((int)acc[i][3]) >> 1);
        *reinterpret_cast<int4*>(dst + (size_t)i*SEQ + 4) =
            make_int4(((int)acc[i][4]) >> 1, ((int)acc[i][5]) >> 1,
                      ((int)acc[i][6]) >> 1, ((int)acc[i][7]) >> 1);
    }

#pragma unroll
    for (int i = 0; i < 8; i++) {
        int row = rowbase + i;
        int mx = (int)0x80000000;
#pragma unroll
        for (int j = 0; j < 8; j++) {
            int col = colbase + j;
            int v = ((int)acc[i][j]) >> 1;
            if (col <= row) mx = max(mx, v);
        }
#pragma unroll
        for (int off = 1; off < 16; off <<= 1)
            mx = max(mx, __shfl_xor_sync(0xffffffffu, mx, off));
        if (cg == 0 && mx != (int)0x80000000)
            atomicMax(&g_rowmax[bh*SEQ + row], mx);
    }
}

// ---------------- sparse AV: balanced row map + single ballot per 128 cols ----------------
__global__ __launch_bounds__(256) void av_kernel() {
    int t = threadIdx.x, lane = t & 31, warp = t >> 5;
    int bh = blockIdx.y;
    int qr = warp * 256 + blockIdx.x;          // balanced: each block's rows span the triangle
    const int* srow = g_scores + (size_t)bh*SEQ*SEQ + (size_t)qr*SEQ;
    const int* Vb = g_v + (size_t)bh * SEQ * HD;

    int m = g_rowmax[bh*SEQ + qr];
    bool hasMasked = (qr < SEQ - 1);
    if (hasMasked) m = max(m, NEGMASK);

    unsigned acc[4] = {0u, 0u, 0u, 0u};
    int d0 = lane * 4;

    // candidate pass: 128 cols per warp-trip, ONE ballot per trip
    for (int k0 = 0; k0 <= qr; k0 += 128) {
        int kb = k0 + lane*4;
        int4 sv = *reinterpret_cast<const int4*>(&srow[kb]);
        int a0 = (kb+0 <= qr) ? min(sv.x - m + 256, 4095) : 0;
        int a1 = (kb+1 <= qr) ? min(sv.y - m + 256, 4095) : 0;
        int a2 = (kb+2 <= qr) ? min(sv.z - m + 256, 4095) : 0;
        int a3 = (kb+3 <= qr) ? min(sv.w - m + 256, 4095) : 0;
        bool any = (a0 > 0) | (a1 > 0) | (a2 > 0) | (a3 > 0);
        unsigned mask = __ballot_sync(0xffffffffu, any);
        while (mask) {
            int src = __ffs(mask) - 1;
            mask &= mask - 1;
            int b0 = __shfl_sync(0xffffffffu, a0, src);
            int b1 = __shfl_sync(0xffffffffu, a1, src);
            int b2 = __shfl_sync(0xffffffffu, a2, src);
            int b3 = __shfl_sync(0xffffffffu, a3, src);
            int kk = k0 + src*4;
            if (b0 > 0) {
                int4 v = *reinterpret_cast<const int4*>(&Vb[(kk+0)*HD + d0]);
                unsigned ua = (unsigned)b0;
                acc[0] += ua*(unsigned)v.x; acc[1] += ua*(unsigned)v.y;
                acc[2] += ua*(unsigned)v.z; acc[3] += ua*(unsigned)v.w;
            }
            if (b1 > 0) {
                int4 v = *reinterpret_cast<const int4*>(&Vb[(kk+1)*HD + d0]);
                unsigned ua = (unsigned)b1;
                acc[0] += ua*(unsigned)v.x; acc[1] += ua*(unsigned)v.y;
                acc[2] += ua*(unsigned)v.z; acc[3] += ua*(unsigned)v.w;
            }
            if (b2 > 0) {
                int4 v = *reinterpret_cast<const int4*>(&Vb[(kk+2)*HD + d0]);
                unsigned ua = (unsigned)b2;
                acc[0] += ua*(unsigned)v.x; acc[1] += ua*(unsigned)v.y;
                acc[2] += ua*(unsigned)v.z; acc[3] += ua*(unsigned)v.w;
            }
            if (b3 > 0) {
                int4 v = *reinterpret_cast<const int4*>(&Vb[(kk+3)*HD + d0]);
                unsigned ua = (unsigned)b3;
                acc[0] += ua*(unsigned)v.x; acc[1] += ua*(unsigned)v.y;
                acc[2] += ua*(unsigned)v.z; acc[3] += ua*(unsigned)v.w;
            }
        }
    }

    int am = NEGMASK - m + 256;
    if (am > 4095) am = 4095;
    if (hasMasked && am > 0) {
        for (int k = qr + 1; k < SEQ; k++) {
            int4 v = *reinterpret_cast<const int4*>(&Vb[k*HD + d0]);
            unsigned ua = (unsigned)am;
            acc[0] += ua * (unsigned)v.x; acc[1] += ua * (unsigned)v.y;
            acc[2] += ua * (unsigned)v.z; acc[3] += ua * (unsigned)v.w;
        }
    }

    unsigned p0 = 0, p1 = 0, p2 = 0;
#pragma unroll
    for (int j = 0; j < 4; j++) {
        int v = ((int)acc[j]) >> 12;
        int dd0 = (int)(signed char)(v & 0xff);
        int r1 = (v - dd0) >> 8;
        int dd1 = (int)(signed char)(r1 & 0xff);
        int dd2 = (r1 - dd1) >> 8;
        p0 |= ((unsigned)dd0 & 255u) << (8*j);
        p1 |= ((unsigned)dd1 & 255u) << (8*j);
        p2 |= ((unsigned)dd2 & 255u) << (8*j);
    }
    int b = bh >> 4, h = bh & (NH-1);
    size_t off = (((size_t)(b*SEQ + qr))*HID + h*HD + d0) >> 2;
    reinterpret_cast<unsigned*>(g_d0)[off] = p0;
    reinterpret_cast<unsigned*>(g_d1)[off] = p1;
    reinterpret_cast<unsigned*>(g_d2)[off] = p2;
}

// ---------------- output projection: IMMA digit planes + cp.async double buffer ----------------
__global__ __launch_bounds__(256) void out_imma_kernel(float* __restrict__ out) {
    __shared__ unsigned char Ap[2][3][64*48];
    __shared__ unsigned char Bs[2][64*48];
    const unsigned* W4 = g_wt + (size_t)3 * (HID*(HID/4));
    const int* bias = g_b32 + 3 * HID;

    int bn = blockIdx.x;
    int bm = blockIdx.y;
    int t = threadIdx.x, lane = t & 31, warp = t >> 5;
    int wm = warp >> 2, wn = warp & 3;

    unsigned aB = (unsigned)__cvta_generic_to_shared(Ap);
    unsigned bB = (unsigned)__cvta_generic_to_shared(Bs);

    int acc[2][2][3][4];
#pragma unroll
    for (int i = 0; i < 2; i++)
#pragma unroll
        for (int j = 0; j < 2; j++)
#pragma unroll
            for (int l = 0; l < 3; l++)
#pragma unroll
                for (int r = 0; r < 4; r++) acc[i][j][l][r] = 0;

    int lrowA = (lane & 7) + ((lane >> 3) & 1) * 8;
    int lkoffA = (lane >= 16) ? 16 : 0;
    int lrowB = (lane & 7);
    int lkoffB = ((lane >> 3) & 1) * 16;

    const unsigned char* P[3] = {g_d0, g_d1, g_d2};

    #define OT_STAGE(ks, buf)                                                              \
        do {                                                                               \
            for (int idx = t; idx < 384; idx += 256) {                                     \
                int l = idx >> 7, j = idx & 127, row = j >> 1, half = j & 1;               \
                cp16(aB + (buf)*9216 + l*3072 + row*48 + half*16,                          \
                     P[l] + ((size_t)(bm*64 + row))*HID + (ks)*32 + half*16);              \
            }                                                                              \
            for (int idx = t; idx < 128; idx += 256) {                                     \
                int row = idx >> 1, half = idx & 1;                                        \
                cp16(bB + (buf)*3072 + row*48 + half*16,                                   \
                     &W4[(size_t)(bn*64 + row)*512 + (ks)*8 + half*4]);                    \
            }                                                                              \
            CP_COMMIT();                                                                   \
        } while (0)

    OT_STAGE(0, 0);
    for (int ks = 0; ks < 64; ks++) {
        int buf = ks & 1;
        if (ks < 63) { OT_STAGE(ks + 1, buf ^ 1); CP_WAIT1(); }
        else         { CP_WAIT0(); }
        __syncthreads();

        unsigned bfr[2][2];
#pragma unroll
        for (int nf = 0; nf < 2; nf++)
            ldsm_x2(bfr[nf], bB + buf*3072 + (wn*16 + nf*8 + lrowB)*48 + lkoffB);
#pragma unroll
        for (int mf = 0; mf < 2; mf++) {
#pragma unroll
            for (int l = 0; l < 3; l++) {
                unsigned afr[4];
                ldsm_x4(afr, aB + buf*9216 + l*3072 + (wm*32 + mf*16 + lrowA)*48 + lkoffA);
#pragma unroll
                for (int nf = 0; nf < 2; nf++)
                    mma_s8s8(acc[mf][nf][l], afr, bfr[nf]);
            }
        }
        __syncthreads();
    }
    #undef OT_STAGE

#pragma unroll
    for (int mf = 0; mf < 2; mf++) {
#pragma unroll
        for (int nf = 0; nf < 2; nf++) {
            int n = bn*64 + wn*16 + nf*8 + 2*(lane & 3);
            unsigned bia0 = (unsigned)bias[n], bia1 = (unsigned)bias[n+1];
#pragma unroll
            for (int half = 0; half < 2; half++) {
                int r = bm*64 + wm*32 + mf*16 + (lane >> 2) + half*8;
                unsigned u0 = (unsigned)acc[mf][nf][0][half*2+0]
                            + ((unsigned)acc[mf][nf][1][half*2+0] << 8)
                            + ((unsigned)acc[mf][nf][2][half*2+0] << 16) + bia0;
                unsigned u1 = (unsigned)acc[mf][nf][0][half*2+1]
                            + ((unsigned)acc[mf][nf][1][half*2+1] << 8)
                            + ((unsigned)acc[mf][nf][2][half*2+1] << 16) + bia1;
                float2 fv = make_float2((float)(((int)u0) >> 7), (float)(((int)u1) >> 7));
                *reinterpret_cast<float2*>(&out[(size_t)r*HID + n]) = fv;
            }
        }
    }
}

// ---------------- launch ----------------
extern "C" void kernel_launch(void* const* d_in, const int* in_sizes, int n_in,
                              void* d_out, int out_size) {
    const void* x  = d_in[0];
    const void* wq = d_in[1]; const void* bq = d_in[2];
    const void* wk = d_in[3]; const void* bk = d_in[4];
    const void* wv = d_in[5]; const void* bv = d_in[6];
    const void* wo = d_in[7]; const void* bo = d_in[8];
    float* out = (float*)d_out;

    convall_kernel<<<dim3(XBLOCKS, 5), 256>>>(x, wq, wk, wv, wo, bq, bk, bv, bo);     // 1
    proj_imma_kernel<<<dim3(16, 32, 3), 256>>>();                                     // 2
    qk_gemm_kernel<<<dim3(NTRI, BH), 256>>>();                                        // 3
    av_kernel<<<dim3(SEQ/8, BH), 256>>>();                                            // 4 (profiled)
    out_imma_kernel<<<dim3(32, 64), 256>>>(out);                                      // 5
}

// round 14
// speedup vs baseline: 1.0500x; 1.0113x over previous
#include <cuda_runtime.h>
#include <cstdint>
#include <math.h>

#define SEQ 2048
#define HID 2048
#define NB  2
#define NH  16
#define HD  128
#define BH  (NB*NH)          // 32
#define MTOT (NB*SEQ)        // 4096
#define NEGMASK (-(1<<20))
#define NQB (SEQ/128)        // 16
#define NTRI (NQB*(NQB+1)/2) // 136
#define FUSE_SMEM 40960

// ---------------- device scratch ----------------
__device__ unsigned g_x4[MTOT * (HID/4)];
__device__ int g_b32[4 * HID];
__device__ unsigned g_wt[4 * HID * (HID/4)];
__device__ int g_q[BH * SEQ * HD];
__device__ int g_k[BH * SEQ * HD];
__device__ int g_v[BH * SEQ * HD];
__device__ int g_scores[(size_t)BH * SEQ * SEQ];
__device__ int g_rowmax[BH * SEQ];
__device__ unsigned char g_d0[MTOT * HID];
__device__ unsigned char g_d1[MTOT * HID];
__device__ unsigned char g_d2[MTOT * HID];

// ---------------- helpers ----------------
__device__ __forceinline__ void mma_u8s8(int* d, const unsigned* a, const unsigned* b) {
    asm volatile(
        "mma.sync.aligned.m16n8k32.row.col.s32.u8.s8.s32 "
        "{%0,%1,%2,%3},{%4,%5,%6,%7},{%8,%9},{%0,%1,%2,%3};"
        : "+r"(d[0]), "+r"(d[1]), "+r"(d[2]), "+r"(d[3])
        : "r"(a[0]), "r"(a[1]), "r"(a[2]), "r"(a[3]), "r"(b[0]), "r"(b[1]));
}
__device__ __forceinline__ void mma_s8s8(int* d, const unsigned* a, const unsigned* b) {
    asm volatile(
        "mma.sync.aligned.m16n8k32.row.col.s32.s8.s8.s32 "
        "{%0,%1,%2,%3},{%4,%5,%6,%7},{%8,%9},{%0,%1,%2,%3};"
        : "+r"(d[0]), "+r"(d[1]), "+r"(d[2]), "+r"(d[3])
        : "r"(a[0]), "r"(a[1]), "r"(a[2]), "r"(a[3]), "r"(b[0]), "r"(b[1]));
}
__device__ __forceinline__ void ldsm_x4(unsigned* r, unsigned addr) {
    asm volatile("ldmatrix.sync.aligned.m8n8.x4.shared.b16 {%0,%1,%2,%3},[%4];"
                 : "=r"(r[0]), "=r"(r[1]), "=r"(r[2]), "=r"(r[3]) : "r"(addr));
}
__device__ __forceinline__ void ldsm_x2(unsigned* r, unsigned addr) {
    asm volatile("ldmatrix.sync.aligned.m8n8.x2.shared.b16 {%0,%1},[%2];"
                 : "=r"(r[0]), "=r"(r[1]) : "r"(addr));
}
__device__ __forceinline__ void cp16(unsigned smaddr, const void* g) {
    asm volatile("cp.async.cg.shared.global [%0], [%1], 16;" :: "r"(smaddr), "l"(g));
}
#define CP_COMMIT() asm volatile("cp.async.commit_group;" ::: "memory")
#define CP_WAIT1()  asm volatile("cp.async.wait_group 1;" ::: "memory")
#define CP_WAIT0()  asm volatile("cp.async.wait_group 0;" ::: "memory")

// ---------------- dtype detection ----------------
__device__ __forceinline__ int classify_word(unsigned w) {
    if (w == 0u) return -1;
    int iv = (int)w;
    if (iv >= -520 && iv <= 520) return 0;
    float f = __int_as_float(w);
    if (isfinite(f) && fabsf(f) <= 520.0f && f != 0.0f && f == rintf(f)) return 1;
    return 2;
}
__device__ int detect_dtype(const unsigned* w, int nwords) {
    __shared__ int votes[3];
    if (threadIdx.x < 3) votes[threadIdx.x] = 0;
    __syncthreads();
    int local[3] = {0,0,0};
    for (int i = threadIdx.x; i < nwords; i += blockDim.x) {
        int c = classify_word(w[i]);
        if (c >= 0) local[c]++;
    }
    for (int c = 0; c < 3; c++) if (local[c]) atomicAdd(&votes[c], local[c]);
    __syncthreads();
    int best = 0;
    if (votes[1] > votes[best]) best = 1;
    if (votes[2] > votes[best]) best = 2;
    return best;
}

// ---------------- ONE conversion kernel ----------------
#define WBLOCKS ((HID*(HID/4) + 255)/256)    // 4096
#define XBLOCKS ((MTOT*(HID/4) + 255)/256)   // 8192
__global__ void convall_kernel(const void* xp,
                               const void* w0, const void* w1, const void* w2, const void* w3,
                               const void* b0, const void* b1, const void* b2, const void* b3) {
    int y = blockIdx.y;
    if (y == 4) {
        int flag = detect_dtype((const unsigned*)xp, 1024);
        int i = blockIdx.x * blockDim.x + threadIdx.x;
        if (i < BH*SEQ) g_rowmax[i] = (int)0x80000000;
        if (i >= MTOT * (HID/4)) return;
        unsigned a, b, c, d;
        if (flag == 1) {
            float4 v = reinterpret_cast<const float4*>(xp)[i];
            a = (unsigned)(int)v.x; b = (unsigned)(int)v.y;
            c = (unsigned)(int)v.z; d = (unsigned)(int)v.w;
        } else {
            int4 v = reinterpret_cast<const int4*>(xp)[i];
            a = (unsigned)v.x; b = (unsigned)v.y; c = (unsigned)v.z; d = (unsigned)v.w;
        }
        g_x4[i] = (a & 255u) | ((b & 255u) << 8) | ((c & 255u) << 16) | ((d & 255u) << 24);
        return;
    }
    int slot = y;
    const void* ws[4] = {w0, w1, w2, w3};
    const void* bs[4] = {b0, b1, b2, b3};
    if ((int)blockIdx.x < WBLOCKS) {
        const void* wp = ws[slot];
        int flag = detect_dtype((const unsigned*)wp, 1024);
        int i = blockIdx.x * blockDim.x + threadIdx.x;
        if (i >= HID * (HID/4)) return;
        int kw = i >> 11;
        int n  = i & (HID-1);
        unsigned b[4];
        if (flag == 2) {
            const unsigned char* p = (const unsigned char*)wp;
#pragma unroll
            for (int j = 0; j < 4; j++) b[j] = p[(size_t)(4*kw+j)*HID + n];
        } else if (flag == 1) {
            const float* p = (const float*)wp;
#pragma unroll
            for (int j = 0; j < 4; j++) b[j] = (unsigned)(int)p[(size_t)(4*kw+j)*HID + n] & 255u;
        } else {
            const int* p = (const int*)wp;
#pragma unroll
            for (int j = 0; j < 4; j++) b[j] = (unsigned)p[(size_t)(4*kw+j)*HID + n] & 255u;
        }
        g_wt[(size_t)slot * (HID*(HID/4)) + (size_t)n*(HID/4) + kw] =
            b[0] | (b[1]<<8) | (b[2]<<16) | (b[3]<<24);
    } else if ((int)blockIdx.x < WBLOCKS + 8) {
        const void* bp = bs[slot];
        int flag = detect_dtype((const unsigned*)bp, 512);
        int i = ((int)blockIdx.x - WBLOCKS) * blockDim.x + threadIdx.x;
        if (i >= HID) return;
        int v;
        if (flag == 1) v = (int)reinterpret_cast<const float*>(bp)[i];
        else           v = reinterpret_cast<const int*>(bp)[i];
        g_b32[slot * HID + i] = v;
    }
}

// ---------------- proj body (IMMA + cp.async), dynamic smem ----------------
__device__ void proj_body(int bn, int bm, int slot, char* dynsm) {
    const unsigned* W4 = g_wt + (size_t)slot * (HID*(HID/4));
    const int* bias = g_b32 + slot * HID;
    int* outp = (slot == 0) ? g_q : (slot == 1) ? g_k : g_v;

    int t = threadIdx.x, lane = t & 31, warp = t >> 5;
    int wm = warp >> 2, wn = warp & 3;

    unsigned aB = (unsigned)__cvta_generic_to_shared(dynsm);          // [2][10240]
    unsigned bB = aB + 20480;                                         // [2][10240]

    int acc[4][4][4];
#pragma unroll
    for (int i = 0; i < 4; i++)
#pragma unroll
        for (int j = 0; j < 4; j++)
#pragma unroll
            for (int r = 0; r < 4; r++) acc[i][j][r] = 0;

    int lrowA = (lane & 7) + ((lane >> 3) & 1) * 8;
    int lkoffA = (lane >= 16) ? 16 : 0;
    int lrowB = (lane & 7);
    int lkoffB = ((lane >> 3) & 1) * 16;

    #define PJ_STAGE(ks, buf)                                                              \
        do {                                                                               \
            for (int idx = t; idx < 512; idx += 256) {                                     \
                int row = idx >> 2, q = idx & 3;                                           \
                cp16(aB + (buf)*10240 + row*80 + q*16,                                     \
                     &g_x4[(size_t)(bm*128 + row)*512 + (ks)*16 + q*4]);                   \
                cp16(bB + (buf)*10240 + row*80 + q*16,                                     \
                     &W4[(size_t)(bn*128 + row)*512 + (ks)*16 + q*4]);                     \
            }                                                                              \
            CP_COMMIT();                                                                   \
        } while (0)

    PJ_STAGE(0, 0);
    for (int ks = 0; ks < 32; ks++) {
        int buf = ks & 1;
        if (ks < 31) { PJ_STAGE(ks + 1, buf ^ 1); CP_WAIT1(); }
        else         { CP_WAIT0(); }
        __syncthreads();
#pragma unroll
        for (int kk = 0; kk < 2; kk++) {
            unsigned bfr[4][2];
#pragma unroll
            for (int nf = 0; nf < 4; nf++)
                ldsm_x2(bfr[nf], bB + buf*10240 + (wn*32 + nf*8 + lrowB)*80 + kk*32 + lkoffB);
            unsigned afr[4][4];
#pragma unroll
            for (int mf = 0; mf < 4; mf++)
                ldsm_x4(afr[mf], aB + buf*10240 + (wm*64 + mf*16 + lrowA)*80 + kk*32 + lkoffA);
#pragma unroll
            for (int mf = 0; mf < 4; mf++)
#pragma unroll
                for (int nf = 0; nf < 4; nf++)
                    mma_u8s8(acc[mf][nf], afr[mf], bfr[nf]);
        }
        __syncthreads();
    }
    #undef PJ_STAGE

#pragma unroll
    for (int mf = 0; mf < 4; mf++) {
#pragma unroll
        for (int nf = 0; nf < 4; nf++) {
            int n = bn*128 + wn*32 + nf*8 + 2*(lane & 3);
            int h = n >> 7, d = n & (HD-1);
            int bia0 = bias[n], bia1 = bias[n+1];
#pragma unroll
            for (int half = 0; half < 2; half++) {
                int r = bm*128 + wm*64 + mf*16 + (lane >> 2) + half*8;
                int b = r >> 11, s = r & (SEQ-1);
                int v0 = (acc[mf][nf][half*2+0] + bia0) >> 6;
                int v1 = (acc[mf][nf][half*2+1] + bia1) >> 6;
                *reinterpret_cast<int2*>(&outp[((size_t)(b*NH + h)*SEQ + s)*HD + d]) = make_int2(v0, v1);
            }
        }
    }
}

__global__ __launch_bounds__(256) void proj_imma_kernel() {
    extern __shared__ char dynsm[];
    proj_body(blockIdx.x, blockIdx.y, blockIdx.z, dynsm);
}

// ---------------- qk body (128x128 IMAD, 8x8 regs, fused rowmax) ----------------
__device__ void qk_body(int blk, int bh, char* dynsm) {
    int (*As)[132] = (int(*)[132])dynsm;
    int (*Bs)[132] = (int(*)[132])(dynsm + 16896);

    int qi = (int)((sqrtf(8.0f*blk + 1.0f) - 1.0f) * 0.5f);
    while ((qi+1)*(qi+2)/2 <= blk) qi++;
    while (qi*(qi+1)/2 > blk) qi--;
    int ki = blk - qi*(qi+1)/2;

    const int* Qb = g_q + (size_t)bh*SEQ*HD + (size_t)(qi*128)*HD;
    const int* Kb = g_k + (size_t)bh*SEQ*HD + (size_t)(ki*128)*HD;
    int t = threadIdx.x;
    int rg = t >> 4, cg = t & 15;

    unsigned acc[8][8];
#pragma unroll
    for (int i = 0; i < 8; i++)
#pragma unroll
        for (int j = 0; j < 8; j++) acc[i][j] = 0u;

    for (int ch = 0; ch < 4; ch++) {
        for (int i = t; i < 128*8; i += 256) {
            int row = i >> 3, g = i & 7;
            int4 qv = *reinterpret_cast<const int4*>(&Qb[row*HD + ch*32 + g*4]);
            As[g*4+0][row] = qv.x; As[g*4+1][row] = qv.y;
            As[g*4+2][row] = qv.z; As[g*4+3][row] = qv.w;
            int4 kv = *reinterpret_cast<const int4*>(&Kb[row*HD + ch*32 + g*4]);
            Bs[g*4+0][row] = kv.x; Bs[g*4+1][row] = kv.y;
            Bs[g*4+2][row] = kv.z; Bs[g*4+3][row] = kv.w;
        }
        __syncthreads();

#pragma unroll 4
        for (int d = 0; d < 32; d++) {
            int4 av0 = *reinterpret_cast<const int4*>(&As[d][rg*8]);
            int4 av1 = *reinterpret_cast<const int4*>(&As[d][rg*8+4]);
            int4 bv0 = *reinterpret_cast<const int4*>(&Bs[d][cg*8]);
            int4 bv1 = *reinterpret_cast<const int4*>(&Bs[d][cg*8+4]);
            int a[8] = {av0.x, av0.y, av0.z, av0.w, av1.x, av1.y, av1.z, av1.w};
            int b[8] = {bv0.x, bv0.y, bv0.z, bv0.w, bv1.x, bv1.y, bv1.z, bv1.w};
#pragma unroll
            for (int i = 0; i < 8; i++)
#pragma unroll
                for (int j = 0; j < 8; j++)
                    acc[i][j] += (unsigned)a[i] * (unsigned)b[j];
        }
        __syncthreads();
    }

    int rowbase = qi*128 + rg*8;
    int colbase = ki*128 + cg*8;
    int* dst = g_scores + (size_t)bh*SEQ*SEQ + (size_t)rowbase*SEQ + colbase;
#pragma unroll
    for (int i = 0; i < 8; i++) {
        *reinterpret_cast<int4*>(dst + (size_t)i*SEQ) =
            make_int4(((int)acc[i][0]) >> 1, ((int)acc[i][1]) >> 1,
                      ((int)acc[i][2]) >> 1, ((int)acc[i][3]) >> 1);
        *reinterpret_cast<int4*>(dst + (size_t)i*SEQ + 4) =
            make_int4(((int)acc[i][4]) >> 1, ((int)acc[i][5]) >> 1,
                      ((int)acc[i][6]) >> 1, ((int)acc[i][7]) >> 1);
    }

#pragma unroll
    for (int i = 0; i < 8; i++) {
        int row = rowbase + i;
        int mx = (int)0x80000000;
#pragma unroll
        for (int j = 0; j < 8; j++) {
            int col = colbase + j;
            int v = ((int)acc[i][j]) >> 1;
            if (col <= row) mx = max(mx, v);
        }
#pragma unroll
        for (int off = 1; off < 16; off <<= 1)
            mx = max(mx, __shfl_xor_sync(0xffffffffu, mx, off));
        if (cg == 0 && mx != (int)0x80000000)
            atomicMax(&g_rowmax[bh*SEQ + row], mx);
    }
}

// ---------------- fused heterogeneous launch: qk blocks + proj(v) blocks ----------------
__global__ __launch_bounds__(256) void qk_projv_kernel() {
    extern __shared__ char dynsm[];
    int i = blockIdx.x;
    if (i < 512) {
        // proj v blocks first (start tensor work immediately)
        proj_body(i & 15, i >> 4, 2, dynsm);
    } else {
        int j = i - 512;
        qk_body(j % NTRI, j / NTRI, dynsm);
    }
}

// ---------------- sparse AV: 2 warps per row ----------------
__global__ __launch_bounds__(256) void av_kernel() {
    __shared__ unsigned part[8][32][4];
    int t = threadIdx.x, lane = t & 31, warp = t >> 5;
    int lr = warp >> 1, h = warp & 1;          // 4 rows x 2 column-halves
    int bh = blockIdx.y;
    int qr = lr * 512 + blockIdx.x;            // blockIdx.x in 0..511
    const int* srow = g_scores + (size_t)bh*SEQ*SEQ + (size_t)qr*SEQ;
    const int* Vb = g_v + (size_t)bh * SEQ * HD;

    int m = g_rowmax[bh*SEQ + qr];
    bool hasMasked = (qr < SEQ - 1);
    if (hasMasked) m = max(m, NEGMASK);

    unsigned acc[4] = {0u, 0u, 0u, 0u};
    int d0 = lane * 4;

    // this warp scans column chunks k0 = h*128, h*128+256, ...
    for (int k0 = h*128; k0 <= qr; k0 += 256) {
        int kb = k0 + lane*4;
        int4 sv = *reinterpret_cast<const int4*>(&srow[kb]);
        int a0 = (kb+0 <= qr) ? min(sv.x - m + 256, 4095) : 0;
        int a1 = (kb+1 <= qr) ? min(sv.y - m + 256, 4095) : 0;
        int a2 = (kb+2 <= qr) ? min(sv.z - m + 256, 4095) : 0;
        int a3 = (kb+3 <= qr) ? min(sv.w - m + 256, 4095) : 0;
        bool any = (a0 > 0) | (a1 > 0) | (a2 > 0) | (a3 > 0);
        unsigned mask = __ballot_sync(0xffffffffu, any);
        while (mask) {
            int src = __ffs(mask) - 1;
            mask &= mask - 1;
            int b0 = __shfl_sync(0xffffffffu, a0, src);
            int b1 = __shfl_sync(0xffffffffu, a1, src);
            int b2 = __shfl_sync(0xffffffffu, a2, src);
            int b3 = __shfl_sync(0xffffffffu, a3, src);
            int kk = k0 + src*4;
            if (b0 > 0) {
                int4 v = *reinterpret_cast<const int4*>(&Vb[(kk+0)*HD + d0]);
                unsigned ua = (unsigned)b0;
                acc[0] += ua*(unsigned)v.x; acc[1] += ua*(unsigned)v.y;
                acc[2] += ua*(unsigned)v.z; acc[3] += ua*(unsigned)v.w;
            }
            if (b1 > 0) {
                int4 v = *reinterpret_cast<const int4*>(&Vb[(kk+1)*HD + d0]);
                unsigned ua = (unsigned)b1;
                acc[0] += ua*(unsigned)v.x; acc[1] += ua*(unsigned)v.y;
                acc[2] += ua*(unsigned)v.z; acc[3] += ua*(unsigned)v.w;
            }
            if (b2 > 0) {
                int4 v = *reinterpret_cast<const int4*>(&Vb[(kk+2)*HD + d0]);
                unsigned ua = (unsigned)b2;
                acc[0] += ua*(unsigned)v.x; acc[1] += ua*(unsigned)v.y;
                acc[2] += ua*(unsigned)v.z; acc[3] += ua*(unsigned)v.w;
            }
            if (b3 > 0) {
                int4 v = *reinterpret_cast<const int4*>(&Vb[(kk+3)*HD + d0]);
                unsigned ua = (unsigned)b3;
                acc[0] += ua*(unsigned)v.x; acc[1] += ua*(unsigned)v.y;
                acc[2] += ua*(unsigned)v.z; acc[3] += ua*(unsigned)v.w;
            }
        }
    }

    // pathological masked contribution: handled by half 0
    int am = NEGMASK - m + 256;
    if (am > 4095) am = 4095;
    if (h == 0 && hasMasked && am > 0) {
        for (int k = qr + 1; k < SEQ; k++) {
            int4 v = *reinterpret_cast<const int4*>(&Vb[k*HD + d0]);
            unsigned ua = (unsigned)am;
            acc[0] += ua * (unsigned)v.x; acc[1] += ua * (unsigned)v.y;
            acc[2] += ua * (unsigned)v.z; acc[3] += ua * (unsigned)v.w;
        }
    }

#pragma unroll
    for (int j = 0; j < 4; j++) part[warp][lane][j] = acc[j];
    __syncthreads();

    if (h == 0) {
#pragma unroll
        for (int j = 0; j < 4; j++) acc[j] += part[warp + 1][lane][j];

        unsigned p0 = 0, p1 = 0, p2 = 0;
#pragma unroll
        for (int j = 0; j < 4; j++) {
            int v = ((int)acc[j]) >> 12;
            int dd0 = (int)(signed char)(v & 0xff);
            int r1 = (v - dd0) >> 8;
            int dd1 = (int)(signed char)(r1 & 0xff);
            int dd2 = (r1 - dd1) >> 8;
            p0 |= ((unsigned)dd0 & 255u) << (8*j);
            p1 |= ((unsigned)dd1 & 255u) << (8*j);
            p2 |= ((unsigned)dd2 & 255u) << (8*j);
        }
        int b = bh >> 4, hh = bh & (NH-1);
        size_t off = (((size_t)(b*SEQ + qr))*HID + hh*HD + d0) >> 2;
        reinterpret_cast<unsigned*>(g_d0)[off] = p0;
        reinterpret_cast<unsigned*>(g_d1)[off] = p1;
        reinterpret_cast<unsigned*>(g_d2)[off] = p2;
    }
}

// ---------------- output projection: IMMA digit planes + cp.async double buffer ----------------
__global__ __launch_bounds__(256) void out_imma_kernel(float* __restrict__ out) {
    __shared__ unsigned char Ap[2][3][64*48];
    __shared__ unsigned char Bs[2][64*48];
    const unsigned* W4 = g_wt + (size_t)3 * (HID*(HID/4));
    const int* bias = g_b32 + 3 * HID;

    int bn = blockIdx.x;
    int bm = blockIdx.y;
    int t = threadIdx.x, lane = t & 31, warp = t >> 5;
    int wm = warp >> 2, wn = warp & 3;

    unsigned aB = (unsigned)__cvta_generic_to_shared(Ap);
    unsigned bB = (unsigned)__cvta_generic_to_shared(Bs);

    int acc[2][2][3][4];
#pragma unroll
    for (int i = 0; i < 2; i++)
#pragma unroll
        for (int j = 0; j < 2; j++)
#pragma unroll
            for (int l = 0; l < 3; l++)
#pragma unroll
                for (int r = 0; r < 4; r++) acc[i][j][l][r] = 0;

    int lrowA = (lane & 7) + ((lane >> 3) & 1) * 8;
    int lkoffA = (lane >= 16) ? 16 : 0;
    int lrowB = (lane & 7);
    int lkoffB = ((lane >> 3) & 1) * 16;

    const unsigned char* P[3] = {g_d0, g_d1, g_d2};

    #define OT_STAGE(ks, buf)                                                              \
        do {                                                                               \
            for (int idx = t; idx < 384; idx += 256) {                                     \
                int l = idx >> 7, j = idx & 127, row = j >> 1, half = j & 1;               \
                cp16(aB + (buf)*9216 + l*3072 + row*48 + half*16,                          \
                     P[l] + ((size_t)(bm*64 + row))*HID + (ks)*32 + half*16);              \
            }                                                                              \
            for (int idx = t; idx < 128; idx += 256) {                                     \
                int row = idx >> 1, half = idx & 1;                                        \
                cp16(bB + (buf)*3072 + row*48 + half*16,                                   \
                     &W4[(size_t)(bn*64 + row)*512 + (ks)*8 + half*4]);                    \
            }                                                                              \
            CP_COMMIT();                                                                   \
        } while (0)

    OT_STAGE(0, 0);
    for (int ks = 0; ks < 64; ks++) {
        int buf = ks & 1;
        if (ks < 63) { OT_STAGE(ks + 1, buf ^ 1); CP_WAIT1(); }
        else         { CP_WAIT0(); }
        __syncthreads();

        unsigned bfr[2][2];
#pragma unroll
        for (int nf = 0; nf < 2; nf++)
            ldsm_x2(bfr[nf], bB + buf*3072 + (wn*16 + nf*8 + lrowB)*48 + lkoffB);
#pragma unroll
        for (int mf = 0; mf < 2; mf++) {
#pragma unroll
            for (int l = 0; l < 3; l++) {
                unsigned afr[4];
                ldsm_x4(afr, aB + buf*9216 + l*3072 + (wm*32 + mf*16 + lrowA)*48 + lkoffA);
#pragma unroll
                for (int nf = 0; nf < 2; nf++)
                    mma_s8s8(acc[mf][nf][l], afr, bfr[nf]);
            }
        }
        __syncthreads();
    }
    #undef OT_STAGE

#pragma unroll
    for (int mf = 0; mf < 2; mf++) {
#pragma unroll
        for (int nf = 0; nf < 2; nf++) {
            int n = bn*64 + wn*16 + nf*8 + 2*(lane & 3);
            unsigned bia0 = (unsigned)bias[n], bia1 = (unsigned)bias[n+1];
#pragma unroll
            for (int half = 0; half < 2; half++) {
                int r = bm*64 + wm*32 + mf*16 + (lane >> 2) + half*8;
                unsigned u0 = (unsigned)acc[mf][nf][0][half*2+0]
                            + ((unsigned)acc[mf][nf][1][half*2+0] << 8)
                            + ((unsigned)acc[mf][nf][2][half*2+0] << 16) + bia0;
                unsigned u1 = (unsigned)acc[mf][nf][0][half*2+1]
                            + ((unsigned)acc[mf][nf][1][half*2+1] << 8)
                            + ((unsigned)acc[mf][nf][2][half*2+1] << 16) + bia1;
                float2 fv = make_float2((float)(((int)u0) >> 7), (float)(((int)u1) >> 7));
                *reinterpret_cast<float2*>(&out[(size_t)r*HID + n]) = fv;
            }
        }
    }
}

// ---------------- launch ----------------
extern "C" void kernel_launch(void* const* d_in, const int* in_sizes, int n_in,
                              void* d_out, int out_size) {
    const void* x  = d_in[0];
    const void* wq = d_in[1]; const void* bq = d_in[2];
    const void* wk = d_in[3]; const void* bk = d_in[4];
    const void* wv = d_in[5]; const void* bv = d_in[6];
    const void* wo = d_in[7]; const void* bo = d_in[8];
    float* out = (float*)d_out;

    convall_kernel<<<dim3(XBLOCKS, 5), 256>>>(x, wq, wk, wv, wo, bq, bk, bv, bo);     // 1
    proj_imma_kernel<<<dim3(16, 32, 2), 256, FUSE_SMEM>>>();                          // 2 (q,k)
    qk_projv_kernel<<<512 + NTRI*BH, 256, FUSE_SMEM>>>();                             // 3 (qk + v-proj)
    av_kernel<<<dim3(512, BH), 256>>>();                                              // 4 (profiled)
    out_imma_kernel<<<dim3(32, 64), 256>>>(out);                                      // 5
}

// round 15
// speedup vs baseline: 1.0909x; 1.0389x over previous
#include <cuda_runtime.h>
#include <cstdint>
#include <math.h>

#define SEQ 2048
#define HID 2048
#define NB  2
#define NH  16
#define HD  128
#define BH  (NB*NH)          // 32
#define MTOT (NB*SEQ)        // 4096
#define NEGMASK (-(1<<20))
#define NQB (SEQ/128)        // 16
#define NTRI (NQB*(NQB+1)/2) // 136
#define FUSE_SMEM 40960

// ---------------- device scratch ----------------
__device__ unsigned g_x4[MTOT * (HID/4)];
__device__ int g_b32[4 * HID];
__device__ unsigned g_wt[4 * HID * (HID/4)];
__device__ int g_q[BH * SEQ * HD];
__device__ int g_k[BH * SEQ * HD];
__device__ int g_v[BH * SEQ * HD];
__device__ int g_scores[(size_t)BH * SEQ * SEQ];
__device__ int g_blkmax[BH * SEQ * NQB];           // per-row per-128-col-block max
__device__ unsigned char g_d0[MTOT * HID];
__device__ unsigned char g_d1[MTOT * HID];
__device__ unsigned char g_d2[MTOT * HID];

// ---------------- helpers ----------------
__device__ __forceinline__ void mma_u8s8(int* d, const unsigned* a, const unsigned* b) {
    asm volatile(
        "mma.sync.aligned.m16n8k32.row.col.s32.u8.s8.s32 "
        "{%0,%1,%2,%3},{%4,%5,%6,%7},{%8,%9},{%0,%1,%2,%3};"
        : "+r"(d[0]), "+r"(d[1]), "+r"(d[2]), "+r"(d[3])
        : "r"(a[0]), "r"(a[1]), "r"(a[2]), "r"(a[3]), "r"(b[0]), "r"(b[1]));
}
__device__ __forceinline__ void mma_s8s8(int* d, const unsigned* a, const unsigned* b) {
    asm volatile(
        "mma.sync.aligned.m16n8k32.row.col.s32.s8.s8.s32 "
        "{%0,%1,%2,%3},{%4,%5,%6,%7},{%8,%9},{%0,%1,%2,%3};"
        : "+r"(d[0]), "+r"(d[1]), "+r"(d[2]), "+r"(d[3])
        : "r"(a[0]), "r"(a[1]), "r"(a[2]), "r"(a[3]), "r"(b[0]), "r"(b[1]));
}
__device__ __forceinline__ void ldsm_x4(unsigned* r, unsigned addr) {
    asm volatile("ldmatrix.sync.aligned.m8n8.x4.shared.b16 {%0,%1,%2,%3},[%4];"
                 : "=r"(r[0]), "=r"(r[1]), "=r"(r[2]), "=r"(r[3]) : "r"(addr));
}
__device__ __forceinline__ void ldsm_x2(unsigned* r, unsigned addr) {
    asm volatile("ldmatrix.sync.aligned.m8n8.x2.shared.b16 {%0,%1},[%2];"
                 : "=r"(r[0]), "=r"(r[1]) : "r"(addr));
}
__device__ __forceinline__ void cp16(unsigned smaddr, const void* g) {
    asm volatile("cp.async.cg.shared.global [%0], [%1], 16;" :: "r"(smaddr), "l"(g));
}
#define CP_COMMIT() asm volatile("cp.async.commit_group;" ::: "memory")
#define CP_WAIT1()  asm volatile("cp.async.wait_group 1;" ::: "memory")
#define CP_WAIT0()  asm volatile("cp.async.wait_group 0;" ::: "memory")

// ---------------- dtype detection ----------------
__device__ __forceinline__ int classify_word(unsigned w) {
    if (w == 0u) return -1;
    int iv = (int)w;
    if (iv >= -520 && iv <= 520) return 0;
    float f = __int_as_float(w);
    if (isfinite(f) && fabsf(f) <= 520.0f && f != 0.0f && f == rintf(f)) return 1;
    return 2;
}
__device__ int detect_dtype(const unsigned* w, int nwords) {
    __shared__ int votes[3];
    if (threadIdx.x < 3) votes[threadIdx.x] = 0;
    __syncthreads();
    int local[3] = {0,0,0};
    for (int i = threadIdx.x; i < nwords; i += blockDim.x) {
        int c = classify_word(w[i]);
        if (c >= 0) local[c]++;
    }
    for (int c = 0; c < 3; c++) if (local[c]) atomicAdd(&votes[c], local[c]);
    __syncthreads();
    int best = 0;
    if (votes[1] > votes[best]) best = 1;
    if (votes[2] > votes[best]) best = 2;
    return best;
}

// ---------------- ONE conversion kernel ----------------
#define WBLOCKS ((HID*(HID/4) + 255)/256)    // 4096
#define XBLOCKS ((MTOT*(HID/4) + 255)/256)   // 8192
__global__ void convall_kernel(const void* xp,
                               const void* w0, const void* w1, const void* w2, const void* w3,
                               const void* b0, const void* b1, const void* b2, const void* b3) {
    int y = blockIdx.y;
    if (y == 4) {
        int flag = detect_dtype((const unsigned*)xp, 1024);
        int i = blockIdx.x * blockDim.x + threadIdx.x;
        if (i >= MTOT * (HID/4)) return;
        unsigned a, b, c, d;
        if (flag == 1) {
            float4 v = reinterpret_cast<const float4*>(xp)[i];
            a = (unsigned)(int)v.x; b = (unsigned)(int)v.y;
            c = (unsigned)(int)v.z; d = (unsigned)(int)v.w;
        } else {
            int4 v = reinterpret_cast<const int4*>(xp)[i];
            a = (unsigned)v.x; b = (unsigned)v.y; c = (unsigned)v.z; d = (unsigned)v.w;
        }
        g_x4[i] = (a & 255u) | ((b & 255u) << 8) | ((c & 255u) << 16) | ((d & 255u) << 24);
        return;
    }
    int slot = y;
    const void* ws[4] = {w0, w1, w2, w3};
    const void* bs[4] = {b0, b1, b2, b3};
    if ((int)blockIdx.x < WBLOCKS) {
        const void* wp = ws[slot];
        int flag = detect_dtype((const unsigned*)wp, 1024);
        int i = blockIdx.x * blockDim.x + threadIdx.x;
        if (i >= HID * (HID/4)) return;
        int kw = i >> 11;
        int n  = i & (HID-1);
        unsigned b[4];
        if (flag == 2) {
            const unsigned char* p = (const unsigned char*)wp;
#pragma unroll
            for (int j = 0; j < 4; j++) b[j] = p[(size_t)(4*kw+j)*HID + n];
        } else if (flag == 1) {
            const float* p = (const float*)wp;
#pragma unroll
            for (int j = 0; j < 4; j++) b[j] = (unsigned)(int)p[(size_t)(4*kw+j)*HID + n] & 255u;
        } else {
            const int* p = (const int*)wp;
#pragma unroll
            for (int j = 0; j < 4; j++) b[j] = (unsigned)p[(size_t)(4*kw+j)*HID + n] & 255u;
        }
        g_wt[(size_t)slot * (HID*(HID/4)) + (size_t)n*(HID/4) + kw] =
            b[0] | (b[1]<<8) | (b[2]<<16) | (b[3]<<24);
    } else if ((int)blockIdx.x < WBLOCKS + 8) {
        const void* bp = bs[slot];
        int flag = detect_dtype((const unsigned*)bp, 512);
        int i = ((int)blockIdx.x - WBLOCKS) * blockDim.x + threadIdx.x;
        if (i >= HID) return;
        int v;
        if (flag == 1) v = (int)reinterpret_cast<const float*>(bp)[i];
        else           v = reinterpret_cast<const int*>(bp)[i];
        g_b32[slot * HID + i] = v;
    }
}

// ---------------- proj body (IMMA + cp.async), dynamic smem ----------------
__device__ void proj_body(int bn, int bm, int slot, char* dynsm) {
    const unsigned* W4 = g_wt + (size_t)slot * (HID*(HID/4));
    const int* bias = g_b32 + slot * HID;
    int* outp = (slot == 0) ? g_q : (slot == 1) ? g_k : g_v;

    int t = threadIdx.x, lane = t & 31, warp = t >> 5;
    int wm = warp >> 2, wn = warp & 3;

    unsigned aB = (unsigned)__cvta_generic_to_shared(dynsm);
    unsigned bB = aB + 20480;

    int acc[4][4][4];
#pragma unroll
    for (int i = 0; i < 4; i++)
#pragma unroll
        for (int j = 0; j < 4; j++)
#pragma unroll
            for (int r = 0; r < 4; r++) acc[i][j][r] = 0;

    int lrowA = (lane & 7) + ((lane >> 3) & 1) * 8;
    int lkoffA = (lane >= 16) ? 16 : 0;
    int lrowB = (lane & 7);
    int lkoffB = ((lane >> 3) & 1) * 16;

    #define PJ_STAGE(ks, buf)                                                              \
        do {                                                                               \
            for (int idx = t; idx < 512; idx += 256) {                                     \
                int row = idx >> 2, q = idx & 3;                                           \
                cp16(aB + (buf)*10240 + row*80 + q*16,                                     \
                     &g_x4[(size_t)(bm*128 + row)*512 + (ks)*16 + q*4]);                   \
                cp16(bB + (buf)*10240 + row*80 + q*16,                                     \
                     &W4[(size_t)(bn*128 + row)*512 + (ks)*16 + q*4]);                     \
            }                                                                              \
            CP_COMMIT();                                                                   \
        } while (0)

    PJ_STAGE(0, 0);
    for (int ks = 0; ks < 32; ks++) {
        int buf = ks & 1;
        if (ks < 31) { PJ_STAGE(ks + 1, buf ^ 1); CP_WAIT1(); }
        else         { CP_WAIT0(); }
        __syncthreads();
#pragma unroll
        for (int kk = 0; kk < 2; kk++) {
            unsigned bfr[4][2];
#pragma unroll
            for (int nf = 0; nf < 4; nf++)
                ldsm_x2(bfr[nf], bB + buf*10240 + (wn*32 + nf*8 + lrowB)*80 + kk*32 + lkoffB);
            unsigned afr[4][4];
#pragma unroll
            for (int mf = 0; mf < 4; mf++)
                ldsm_x4(afr[mf], aB + buf*10240 + (wm*64 + mf*16 + lrowA)*80 + kk*32 + lkoffA);
#pragma unroll
            for (int mf = 0; mf < 4; mf++)
#pragma unroll
                for (int nf = 0; nf < 4; nf++)
                    mma_u8s8(acc[mf][nf], afr[mf], bfr[nf]);
        }
        __syncthreads();
    }
    #undef PJ_STAGE

#pragma unroll
    for (int mf = 0; mf < 4; mf++) {
#pragma unroll
        for (int nf = 0; nf < 4; nf++) {
            int n = bn*128 + wn*32 + nf*8 + 2*(lane & 3);
            int h = n >> 7, d = n & (HD-1);
            int bia0 = bias[n], bia1 = bias[n+1];
#pragma unroll
            for (int half = 0; half < 2; half++) {
                int r = bm*128 + wm*64 + mf*16 + (lane >> 2) + half*8;
                int b = r >> 11, s = r & (SEQ-1);
                int v0 = (acc[mf][nf][half*2+0] + bia0) >> 6;
                int v1 = (acc[mf][nf][half*2+1] + bia1) >> 6;
                *reinterpret_cast<int2*>(&outp[((size_t)(b*NH + h)*SEQ + s)*HD + d]) = make_int2(v0, v1);
            }
        }
    }
}

__global__ __launch_bounds__(256) void proj_imma_kernel() {
    extern __shared__ char dynsm[];
    proj_body(blockIdx.x, blockIdx.y, blockIdx.z, dynsm);
}

// ---------------- qk body: 128x128 IMAD + per-block rowmax publication ----------------
__device__ void qk_body(int blk, int bh, char* dynsm) {
    int (*As)[132] = (int(*)[132])dynsm;
    int (*Bs)[132] = (int(*)[132])(dynsm + 16896);

    int qi = (int)((sqrtf(8.0f*blk + 1.0f) - 1.0f) * 0.5f);
    while ((qi+1)*(qi+2)/2 <= blk) qi++;
    while (qi*(qi+1)/2 > blk) qi--;
    int ki = blk - qi*(qi+1)/2;

    const int* Qb = g_q + (size_t)bh*SEQ*HD + (size_t)(qi*128)*HD;
    const int* Kb = g_k + (size_t)bh*SEQ*HD + (size_t)(ki*128)*HD;
    int t = threadIdx.x;
    int rg = t >> 4, cg = t & 15;

    unsigned acc[8][8];
#pragma unroll
    for (int i = 0; i < 8; i++)
#pragma unroll
        for (int j = 0; j < 8; j++) acc[i][j] = 0u;

    for (int ch = 0; ch < 4; ch++) {
        for (int i = t; i < 128*8; i += 256) {
            int row = i >> 3, g = i & 7;
            int4 qv = *reinterpret_cast<const int4*>(&Qb[row*HD + ch*32 + g*4]);
            As[g*4+0][row] = qv.x; As[g*4+1][row] = qv.y;
            As[g*4+2][row] = qv.z; As[g*4+3][row] = qv.w;
            int4 kv = *reinterpret_cast<const int4*>(&Kb[row*HD + ch*32 + g*4]);
            Bs[g*4+0][row] = kv.x; Bs[g*4+1][row] = kv.y;
            Bs[g*4+2][row] = kv.z; Bs[g*4+3][row] = kv.w;
        }
        __syncthreads();

#pragma unroll 4
        for (int d = 0; d < 32; d++) {
            int4 av0 = *reinterpret_cast<const int4*>(&As[d][rg*8]);
            int4 av1 = *reinterpret_cast<const int4*>(&As[d][rg*8+4]);
            int4 bv0 = *reinterpret_cast<const int4*>(&Bs[d][cg*8]);
            int4 bv1 = *reinterpret_cast<const int4*>(&Bs[d][cg*8+4]);
            int a[8] = {av0.x, av0.y, av0.z, av0.w, av1.x, av1.y, av1.z, av1.w};
            int b[8] = {bv0.x, bv0.y, bv0.z, bv0.w, bv1.x, bv1.y, bv1.z, bv1.w};
#pragma unroll
            for (int i = 0; i < 8; i++)
#pragma unroll
                for (int j = 0; j < 8; j++)
                    acc[i][j] += (unsigned)a[i] * (unsigned)b[j];
        }
        __syncthreads();
    }

    int rowbase = qi*128 + rg*8;
    int colbase = ki*128 + cg*8;
    int* dst = g_scores + (size_t)bh*SEQ*SEQ + (size_t)rowbase*SEQ + colbase;
#pragma unroll
    for (int i = 0; i < 8; i++) {
        *reinterpret_cast<int4*>(dst + (size_t)i*SEQ) =
            make_int4(((int)acc[i][0]) >> 1, ((int)acc[i][1]) >> 1,
                      ((int)acc[i][2]) >> 1, ((int)acc[i][3]) >> 1);
        *reinterpret_cast<int4*>(dst + (size_t)i*SEQ + 4) =
            make_int4(((int)acc[i][4]) >> 1, ((int)acc[i][5]) >> 1,
                      ((int)acc[i][6]) >> 1, ((int)acc[i][7]) >> 1);
    }

    // per-(row, k-block) max publication — unique writer, no atomics
#pragma unroll
    for (int i = 0; i < 8; i++) {
        int row = rowbase + i;
        int mx = (int)0x80000000;
#pragma unroll
        for (int j = 0; j < 8; j++) {
            int col = colbase + j;
            int v = ((int)acc[i][j]) >> 1;
            if (col <= row) mx = max(mx, v);
        }
#pragma unroll
        for (int off = 1; off < 16; off <<= 1)
            mx = max(mx, __shfl_xor_sync(0xffffffffu, mx, off));
        if (cg == 0)
            g_blkmax[(bh*SEQ + row)*NQB + ki] = mx;
    }
}

// ---------------- fused heterogeneous launch: qk blocks + proj(v) blocks ----------------
__global__ __launch_bounds__(256) void qk_projv_kernel() {
    extern __shared__ char dynsm[];
    int i = blockIdx.x;
    if (i < 512) {
        proj_body(i & 15, i >> 4, 2, dynsm);
    } else {
        int j = i - 512;
        qk_body(j % NTRI, j / NTRI, dynsm);
    }
}

// ---------------- sparse AV with block skipping (warp per row) ----------------
__global__ __launch_bounds__(256) void av_kernel() {
    int t = threadIdx.x, lane = t & 31, warp = t >> 5;
    int bh = blockIdx.y;
    int qr = warp * 256 + blockIdx.x;          // balanced row map
    const int* srow = g_scores + (size_t)bh*SEQ*SEQ + (size_t)qr*SEQ;
    const int* Vb = g_v + (size_t)bh * SEQ * HD;

    int nb = (qr >> 7) + 1;                    // k-blocks covering [0, qr]
    const int* bmx = g_blkmax + (bh*SEQ + qr)*NQB;
    int bv = (lane < nb) ? bmx[lane] : (int)0x80000000;
    int m = bv;
#pragma unroll
    for (int off = 16; off; off >>= 1) m = max(m, __shfl_xor_sync(0xffffffffu, m, off));
    bool hasMasked = (qr < SEQ - 1);
    if (hasMasked) m = max(m, NEGMASK);

    unsigned acc[4] = {0u, 0u, 0u, 0u};
    int d0 = lane * 4;
    int thresh = m - 256;                      // block may contribute iff blkmax > thresh

    unsigned bmask = __ballot_sync(0xffffffffu, lane < nb && bv > thresh);
    while (bmask) {
        int blkid = __ffs(bmask) - 1;
        bmask &= bmask - 1;
        int k0 = blkid * 128;
        int kb = k0 + lane*4;
        int4 sv = *reinterpret_cast<const int4*>(&srow[kb]);
        int a0 = (kb+0 <= qr) ? min(sv.x - m + 256, 4095) : 0;
        int a1 = (kb+1 <= qr) ? min(sv.y - m + 256, 4095) : 0;
        int a2 = (kb+2 <= qr) ? min(sv.z - m + 256, 4095) : 0;
        int a3 = (kb+3 <= qr) ? min(sv.w - m + 256, 4095) : 0;
        bool any = (a0 > 0) | (a1 > 0) | (a2 > 0) | (a3 > 0);
        unsigned mask = __ballot_sync(0xffffffffu, any);
        while (mask) {
            int src = __ffs(mask) - 1;
            mask &= mask - 1;
            int b0 = __shfl_sync(0xffffffffu, a0, src);
            int b1 = __shfl_sync(0xffffffffu, a1, src);
            int b2 = __shfl_sync(0xffffffffu, a2, src);
            int b3 = __shfl_sync(0xffffffffu, a3, src);
            int kk = k0 + src*4;
            if (b0 > 0) {
                int4 v = *reinterpret_cast<const int4*>(&Vb[(kk+0)*HD + d0]);
                unsigned ua = (unsigned)b0;
                acc[0] += ua*(unsigned)v.x; acc[1] += ua*(unsigned)v.y;
                acc[2] += ua*(unsigned)v.z; acc[3] += ua*(unsigned)v.w;
            }
            if (b1 > 0) {
                int4 v = *reinterpret_cast<const int4*>(&Vb[(kk+1)*HD + d0]);
                unsigned ua = (unsigned)b1;
                acc[0] += ua*(unsigned)v.x; acc[1] += ua*(unsigned)v.y;
                acc[2] += ua*(unsigned)v.z; acc[3] += ua*(unsigned)v.w;
            }
            if (b2 > 0) {
                int4 v = *reinterpret_cast<const int4*>(&Vb[(kk+2)*HD + d0]);
                unsigned ua = (unsigned)b2;
                acc[0] += ua*(unsigned)v.x; acc[1] += ua*(unsigned)v.y;
                acc[2] += ua*(unsigned)v.z; acc[3] += ua*(unsigned)v.w;
            }
            if (b3 > 0) {
                int4 v = *reinterpret_cast<const int4*>(&Vb[(kk+3)*HD + d0]);
                unsigned ua = (unsigned)b3;
                acc[0] += ua*(unsigned)v.x; acc[1] += ua*(unsigned)v.y;
                acc[2] += ua*(unsigned)v.z; acc[3] += ua*(unsigned)v.w;
            }
        }
    }

    // pathological: masked entries contribute
    int am = NEGMASK - m + 256;
    if (am > 4095) am = 4095;
    if (hasMasked && am > 0) {
        for (int k = qr + 1; k < SEQ; k++) {
            int4 v = *reinterpret_cast<const int4*>(&Vb[k*HD + d0]);
            unsigned ua = (unsigned)am;
            acc[0] += ua * (unsigned)v.x; acc[1] += ua * (unsigned)v.y;
            acc[2] += ua * (unsigned)v.z; acc[3] += ua * (unsigned)v.w;
        }
    }

    unsigned p0 = 0, p1 = 0, p2 = 0;
#pragma unroll
    for (int j = 0; j < 4; j++) {
        int v = ((int)acc[j]) >> 12;
        int dd0 = (int)(signed char)(v & 0xff);
        int r1 = (v - dd0) >> 8;
        int dd1 = (int)(signed char)(r1 & 0xff);
        int dd2 = (r1 - dd1) >> 8;
        p0 |= ((unsigned)dd0 & 255u) << (8*j);
        p1 |= ((unsigned)dd1 & 255u) << (8*j);
        p2 |= ((unsigned)dd2 & 255u) << (8*j);
    }
    int b = bh >> 4, h = bh & (NH-1);
    size_t off = (((size_t)(b*SEQ + qr))*HID + h*HD + d0) >> 2;
    reinterpret_cast<unsigned*>(g_d0)[off] = p0;
    reinterpret_cast<unsigned*>(g_d1)[off] = p1;
    reinterpret_cast<unsigned*>(g_d2)[off] = p2;
}

// ---------------- output projection: IMMA digit planes + cp.async double buffer ----------------
__global__ __launch_bounds__(256) void out_imma_kernel(float* __restrict__ out) {
    __shared__ unsigned char Ap[2][3][64*48];
    __shared__ unsigned char Bs[2][64*48];
    const unsigned* W4 = g_wt + (size_t)3 * (HID*(HID/4));
    const int* bias = g_b32 + 3 * HID;

    int bn = blockIdx.x;
    int bm = blockIdx.y;
    int t = threadIdx.x, lane = t & 31, warp = t >> 5;
    int wm = warp >> 2, wn = warp & 3;

    unsigned aB = (unsigned)__cvta_generic_to_shared(Ap);
    unsigned bB = (unsigned)__cvta_generic_to_shared(Bs);

    int acc[2][2][3][4];
#pragma unroll
    for (int i = 0; i < 2; i++)
#pragma unroll
        for (int j = 0; j < 2; j++)
#pragma unroll
            for (int l = 0; l < 3; l++)
#pragma unroll
                for (int r = 0; r < 4; r++) acc[i][j][l][r] = 0;

    int lrowA = (lane & 7) + ((lane >> 3) & 1) * 8;
    int lkoffA = (lane >= 16) ? 16 : 0;
    int lrowB = (lane & 7);
    int lkoffB = ((lane >> 3) & 1) * 16;

    const unsigned char* P[3] = {g_d0, g_d1, g_d2};

    #define OT_STAGE(ks, buf)                                                              \
        do {                                                                               \
            for (int idx = t; idx < 384; idx += 256) {                                     \
                int l = idx >> 7, j = idx & 127, row = j >> 1, half = j & 1;               \
                cp16(aB + (buf)*9216 + l*3072 + row*48 + half*16,                          \
                     P[l] + ((size_t)(bm*64 + row))*HID + (ks)*32 + half*16);              \
            }                                                                              \
            for (int idx = t; idx < 128; idx += 256) {                                     \
                int row = idx >> 1, half = idx & 1;                                        \
                cp16(bB + (buf)*3072 + row*48 + half*16,                                   \
                     &W4[(size_t)(bn*64 + row)*512 + (ks)*8 + half*4]);                    \
            }                                                                              \
            CP_COMMIT();                                                                   \
        } while (0)

    OT_STAGE(0, 0);
    for (int ks = 0; ks < 64; ks++) {
        int buf = ks & 1;
        if (ks < 63) { OT_STAGE(ks + 1, buf ^ 1); CP_WAIT1(); }
        else         { CP_WAIT0(); }
        __syncthreads();

        unsigned bfr[2][2];
#pragma unroll
        for (int nf = 0; nf < 2; nf++)
            ldsm_x2(bfr[nf], bB + buf*3072 + (wn*16 + nf*8 + lrowB)*48 + lkoffB);
#pragma unroll
        for (int mf = 0; mf < 2; mf++) {
#pragma unroll
            for (int l = 0; l < 3; l++) {
                unsigned afr[4];
                ldsm_x4(afr, aB + buf*9216 + l*3072 + (wm*32 + mf*16 + lrowA)*48 + lkoffA);
#pragma unroll
                for (int nf = 0; nf < 2; nf++)
                    mma_s8s8(acc[mf][nf][l], afr, bfr[nf]);
            }
        }
        __syncthreads();
    }
    #undef OT_STAGE

#pragma unroll
    for (int mf = 0; mf < 2; mf++) {
#pragma unroll
        for (int nf = 0; nf < 2; nf++) {
            int n = bn*64 + wn*16 + nf*8 + 2*(lane & 3);
            unsigned bia0 = (unsigned)bias[n], bia1 = (unsigned)bias[n+1];
#pragma unroll
            for (int half = 0; half < 2; half++) {
                int r = bm*64 + wm*32 + mf*16 + (lane >> 2) + half*8;
                unsigned u0 = (unsigned)acc[mf][nf][0][half*2+0]
                            + ((unsigned)acc[mf][nf][1][half*2+0] << 8)
                            + ((unsigned)acc[mf][nf][2][half*2+0] << 16) + bia0;
                unsigned u1 = (unsigned)acc[mf][nf][0][half*2+1]
                            + ((unsigned)acc[mf][nf][1][half*2+1] << 8)
                            + ((unsigned)acc[mf][nf][2][half*2+1] << 16) + bia1;
                float2 fv = make_float2((float)(((int)u0) >> 7), (float)(((int)u1) >> 7));
                *reinterpret_cast<float2*>(&out[(size_t)r*HID + n]) = fv;
            }
        }
    }
}

// ---------------- launch ----------------
extern "C" void kernel_launch(void* const* d_in, const int* in_sizes, int n_in,
                              void* d_out, int out_size) {
    const void* x  = d_in[0];
    const void* wq = d_in[1]; const void* bq = d_in[2];
    const void* wk = d_in[3]; const void* bk = d_in[4];
    const void* wv = d_in[5]; const void* bv = d_in[6];
    const void* wo = d_in[7]; const void* bo = d_in[8];
    float* out = (float*)d_out;

    convall_kernel<<<dim3(XBLOCKS, 5), 256>>>(x, wq, wk, wv, wo, bq, bk, bv, bo);     // 1
    proj_imma_kernel<<<dim3(16, 32, 2), 256, FUSE_SMEM>>>();                          // 2 (q,k)
    qk_projv_kernel<<<512 + NTRI*BH, 256, FUSE_SMEM>>>();                             // 3 (qk + v-proj)
    av_kernel<<<dim3(256, BH), 256>>>();                                              // 4 (profiled)
    out_imma_kernel<<<dim3(32, 64), 256>>>(out);                                      // 5
}